// round 2
// baseline (speedup 1.0000x reference)
#include <cuda_runtime.h>
#include <math.h>

#define B_SZ   65536
#define IN_D   512
#define H_DIM  512
#define H3     1536
#define NHEAD  8
#define HDIM   64
#define LN_EPS 1e-5f

// Scratch (device globals; aliased across pipeline stages):
//   g_buf1: h [B,1536]  ->  ctx [3B,512]   (same byte count)
//   g_buf2: qkv [3B,1536] -> attn_out [3B,512] (attn_out uses first 3B*512)
__device__ float g_buf1[(size_t)B_SZ * H3];
__device__ float g_buf2[(size_t)B_SZ * 3 * H3];

// ---------------------------------------------------------------------------
// C[m,n] = sum_k A[m,k] * W[n,k] + bias[n]
// A: [M,K] row-major, W: [N,K] row-major (i.e. x @ W^T). K % 8 == 0,
// M % 128 == 0, N % 128 == 0 for this problem, so no bounds checks.
// BM=BN=128, BK=8, 256 threads, 8x8 microtile per thread.
// ---------------------------------------------------------------------------
__global__ __launch_bounds__(256) void sgemm_tn_bias(
    const float* __restrict__ A, const float* __restrict__ W,
    const float* __restrict__ bias, float* __restrict__ C,
    int M, int N, int K)
{
    __shared__ float As[8][128];
    __shared__ float Bs[8][128];

    const int tid = threadIdx.x;
    const int m0 = blockIdx.y * 128;
    const int n0 = blockIdx.x * 128;

    const int lr = tid >> 1;         // 0..127 (row within tile for loading)
    const int lc = (tid & 1) * 4;    // 0 or 4 (k-offset for float4 load)
    const int tx = tid & 15;         // 0..15  (output col group)
    const int ty = tid >> 4;         // 0..15  (output row group)

    float acc[8][8];
    #pragma unroll
    for (int i = 0; i < 8; i++)
        #pragma unroll
        for (int j = 0; j < 8; j++) acc[i][j] = 0.0f;

    const float* Aptr = A + (size_t)(m0 + lr) * K + lc;
    const float* Wptr = W + (size_t)(n0 + lr) * K + lc;

    for (int k0 = 0; k0 < K; k0 += 8) {
        const float4 a = *reinterpret_cast<const float4*>(Aptr + k0);
        const float4 b = *reinterpret_cast<const float4*>(Wptr + k0);
        __syncthreads();   // previous iteration's smem reads done
        As[lc + 0][lr] = a.x; As[lc + 1][lr] = a.y;
        As[lc + 2][lr] = a.z; As[lc + 3][lr] = a.w;
        Bs[lc + 0][lr] = b.x; Bs[lc + 1][lr] = b.y;
        Bs[lc + 2][lr] = b.z; Bs[lc + 3][lr] = b.w;
        __syncthreads();
        #pragma unroll
        for (int kk = 0; kk < 8; kk++) {
            float4 ra0 = *reinterpret_cast<const float4*>(&As[kk][ty * 8]);
            float4 ra1 = *reinterpret_cast<const float4*>(&As[kk][ty * 8 + 4]);
            float4 rb0 = *reinterpret_cast<const float4*>(&Bs[kk][tx * 8]);
            float4 rb1 = *reinterpret_cast<const float4*>(&Bs[kk][tx * 8 + 4]);
            float ra[8] = {ra0.x, ra0.y, ra0.z, ra0.w, ra1.x, ra1.y, ra1.z, ra1.w};
            float rb[8] = {rb0.x, rb0.y, rb0.z, rb0.w, rb1.x, rb1.y, rb1.z, rb1.w};
            #pragma unroll
            for (int i = 0; i < 8; i++)
                #pragma unroll
                for (int j = 0; j < 8; j++)
                    acc[i][j] = fmaf(ra[i], rb[j], acc[i][j]);
        }
    }

    #pragma unroll
    for (int i = 0; i < 8; i++) {
        const int m = m0 + ty * 8 + i;
        #pragma unroll
        for (int j = 0; j < 8; j += 4) {
            const int n = n0 + tx * 8 + j;
            float4 o;
            o.x = acc[i][j + 0] + bias[n + 0];
            o.y = acc[i][j + 1] + bias[n + 1];
            o.z = acc[i][j + 2] + bias[n + 2];
            o.w = acc[i][j + 3] + bias[n + 3];
            *reinterpret_cast<float4*>(C + (size_t)m * N + n) = o;
        }
    }
}

// ---------------------------------------------------------------------------
// In-place LayerNorm(1536) + affine + ReLU. One block (256 thr) per row.
// ---------------------------------------------------------------------------
__global__ __launch_bounds__(256) void ln_relu_kernel(
    float* __restrict__ h, const float* __restrict__ g,
    const float* __restrict__ bp)
{
    float* hr = h + (size_t)blockIdx.x * H3;
    const int tid = threadIdx.x;

    float v[6];
    float s = 0.0f, ss = 0.0f;
    #pragma unroll
    for (int i = 0; i < 6; i++) {
        float x = hr[tid + i * 256];
        v[i] = x;
        s += x;
        ss += x * x;
    }
    #pragma unroll
    for (int o = 16; o > 0; o >>= 1) {
        s  += __shfl_xor_sync(0xffffffffu, s, o);
        ss += __shfl_xor_sync(0xffffffffu, ss, o);
    }
    __shared__ float red[2][8];
    const int wid = tid >> 5, lid = tid & 31;
    if (lid == 0) { red[0][wid] = s; red[1][wid] = ss; }
    __syncthreads();
    s = 0.0f; ss = 0.0f;
    #pragma unroll
    for (int w = 0; w < 8; w++) { s += red[0][w]; ss += red[1][w]; }

    const float mean = s * (1.0f / H3);
    const float var  = ss * (1.0f / H3) - mean * mean;
    const float rstd = rsqrtf(var + LN_EPS);

    #pragma unroll
    for (int i = 0; i < 6; i++) {
        const int c = tid + i * 256;
        float y = (v[i] - mean) * rstd * g[c] + bp[c];
        hr[c] = fmaxf(y, 0.0f);
    }
}

// ---------------------------------------------------------------------------
// Attention: one warp per (batch, head). 3-token seq, head dim 64.
// qkv: [3B, 1536] rows r=3b+t; q cols [0,512), k [512,1024), v [1024,1536).
// ctx: [3B, 512].
// ---------------------------------------------------------------------------
__global__ __launch_bounds__(256) void attn_kernel(
    const float* __restrict__ qkv, float* __restrict__ ctx)
{
    const int gw   = blockIdx.x * 8 + (threadIdx.x >> 5); // b*NHEAD + head
    const int lane = threadIdx.x & 31;
    const int b    = gw >> 3;
    const int head = gw & 7;
    const int d0   = lane * 2;

    const float* base = qkv + (size_t)b * 3 * H3 + head * HDIM + d0;
    float2 q[3], k[3], v[3];
    #pragma unroll
    for (int t = 0; t < 3; t++) {
        const float* r = base + (size_t)t * H3;
        q[t] = *reinterpret_cast<const float2*>(r);
        k[t] = *reinterpret_cast<const float2*>(r + H_DIM);
        v[t] = *reinterpret_cast<const float2*>(r + 2 * H_DIM);
    }

    float s[3][3];
    #pragma unroll
    for (int i = 0; i < 3; i++)
        #pragma unroll
        for (int j = 0; j < 3; j++)
            s[i][j] = q[i].x * k[j].x + q[i].y * k[j].y;
    #pragma unroll
    for (int o = 16; o > 0; o >>= 1)
        #pragma unroll
        for (int i = 0; i < 3; i++)
            #pragma unroll
            for (int j = 0; j < 3; j++)
                s[i][j] += __shfl_xor_sync(0xffffffffu, s[i][j], o);

    float p[3][3];
    #pragma unroll
    for (int i = 0; i < 3; i++) {
        float a0 = s[i][0] * 0.125f, a1 = s[i][1] * 0.125f, a2 = s[i][2] * 0.125f;
        float m = fmaxf(a0, fmaxf(a1, a2));
        float e0 = expf(a0 - m), e1 = expf(a1 - m), e2 = expf(a2 - m);
        float inv = 1.0f / (e0 + e1 + e2);
        p[i][0] = e0 * inv; p[i][1] = e1 * inv; p[i][2] = e2 * inv;
    }

    #pragma unroll
    for (int i = 0; i < 3; i++) {
        float2 c;
        c.x = p[i][0] * v[0].x + p[i][1] * v[1].x + p[i][2] * v[2].x;
        c.y = p[i][0] * v[0].y + p[i][1] * v[1].y + p[i][2] * v[2].y;
        *reinterpret_cast<float2*>(
            ctx + (size_t)(b * 3 + i) * H_DIM + head * HDIM + d0) = c;
    }
}

// ---------------------------------------------------------------------------
// Gumbel softmax over the 3 tokens; writes (y0 | y1 | y2), each [B, 512].
// attn: [3B, 512] logits (bias already added). gum: [B, 3, 512].
// ---------------------------------------------------------------------------
__global__ __launch_bounds__(256) void gumbel_out_kernel(
    const float* __restrict__ attn, const float* __restrict__ gum,
    float* __restrict__ out)
{
    const size_t idx = (size_t)blockIdx.x * 256 + threadIdx.x;  // b*512 + c
    const size_t b = idx >> 9;
    const int    c = (int)(idx & 511);

    const float l0 = attn[(b * 3 + 0) * H_DIM + c] + gum[b * H3 + c];
    const float l1 = attn[(b * 3 + 1) * H_DIM + c] + gum[b * H3 + 512 + c];
    const float l2 = attn[(b * 3 + 2) * H_DIM + c] + gum[b * H3 + 1024 + c];

    const float m  = fmaxf(l0, fmaxf(l1, l2));
    const float e0 = expf(l0 - m), e1 = expf(l1 - m), e2 = expf(l2 - m);
    const float r  = 1.0f / (e0 + e1 + e2);

    out[idx]                               = e0 * r;
    out[(size_t)B_SZ * H_DIM + idx]        = e1 * r;
    out[(size_t)2 * B_SZ * H_DIM + idx]    = e2 * r;
}

// ---------------------------------------------------------------------------
extern "C" void kernel_launch(void* const* d_in, const int* in_sizes, int n_in,
                              void* d_out, int out_size)
{
    const float* x    = (const float*)d_in[0];
    const float* W_fc = (const float*)d_in[1];
    const float* b_fc = (const float*)d_in[2];
    const float* ln_g = (const float*)d_in[3];
    const float* ln_b = (const float*)d_in[4];
    const float* Wqkv = (const float*)d_in[5];
    const float* bqkv = (const float*)d_in[6];
    const float* Wo   = (const float*)d_in[7];
    const float* bo   = (const float*)d_in[8];
    const float* gum  = (const float*)d_in[9];
    float* out = (float*)d_out;

    float *buf1, *buf2;
    cudaGetSymbolAddress((void**)&buf1, g_buf1);
    cudaGetSymbolAddress((void**)&buf2, g_buf2);

    dim3 blk(256);

    // 1) h = x @ W_fc^T + b_fc                      [B, 1536]
    sgemm_tn_bias<<<dim3(H3 / 128, B_SZ / 128), blk>>>(
        x, W_fc, b_fc, buf1, B_SZ, H3, IN_D);

    // 2) LayerNorm + ReLU in place
    ln_relu_kernel<<<B_SZ, blk>>>(buf1, ln_g, ln_b);

    // 3) qkv = h3 @ Wqkv^T + bqkv  (h viewed as [3B, 512]) -> [3B, 1536]
    sgemm_tn_bias<<<dim3(H3 / 128, (3 * B_SZ) / 128), blk>>>(
        buf1, Wqkv, bqkv, buf2, 3 * B_SZ, H3, H_DIM);

    // 4) per-(b,head) attention: qkv -> ctx [3B, 512]  (ctx aliases buf1)
    attn_kernel<<<B_SZ, blk>>>(buf2, buf1);

    // 5) attn_out = ctx @ Wo^T + bo -> [3B, 512]  (aliases buf2)
    sgemm_tn_bias<<<dim3(H_DIM / 128, (3 * B_SZ) / 128), blk>>>(
        buf1, Wo, bo, buf2, 3 * B_SZ, H_DIM, H_DIM);

    // 6) gumbel softmax over tokens -> out (y0|y1|y2)
    gumbel_out_kernel<<<(B_SZ * H_DIM) / 256, blk>>>(buf2, gum, out);
}

// round 4
// speedup vs baseline: 2.4749x; 2.4749x over previous
#include <cuda_runtime.h>
#include <cuda_bf16.h>
#include <cstdint>
#include <math.h>

#define B_SZ   65536
#define IN_D   512
#define H_DIM  512
#define H3     1536
#define NHEAD  8
#define HDIM   64
#define LN_EPS 1e-5f

#define GK     512          // K for all three GEMMs
#define GBM    128
#define GBN    64
#define GBK    64
#define SROW   72           // smem row stride in bf16 elems (144B: conflict-free)
#define SROWB  144
#define SA_BYTES (128 * SROWB)   // 18432
#define SB_BYTES (64 * SROWB)    //  9216
#define GEMM_SMEM (2 * SA_BYTES + 2 * SB_BYTES)  // 55296

// ---------------------------------------------------------------------------
// Scratch (device globals)
// ---------------------------------------------------------------------------
__device__ float g_f32[(size_t)B_SZ * 3 * H3];                 // h -> qkv -> attn_out
__device__ __nv_bfloat16 g_x_hi[(size_t)B_SZ * IN_D];
__device__ __nv_bfloat16 g_x_lo[(size_t)B_SZ * IN_D];
__device__ __nv_bfloat16 g_h_hi[(size_t)B_SZ * H3];            // viewed as [3B,512]
__device__ __nv_bfloat16 g_h_lo[(size_t)B_SZ * H3];
__device__ __nv_bfloat16 g_c_hi[(size_t)B_SZ * 3 * H_DIM];     // ctx [3B,512]
__device__ __nv_bfloat16 g_c_lo[(size_t)B_SZ * 3 * H_DIM];
__device__ __nv_bfloat16 g_wfc_hi[(size_t)H3 * IN_D];
__device__ __nv_bfloat16 g_wfc_lo[(size_t)H3 * IN_D];
__device__ __nv_bfloat16 g_wqkv_hi[(size_t)H3 * H_DIM];
__device__ __nv_bfloat16 g_wqkv_lo[(size_t)H3 * H_DIM];
__device__ __nv_bfloat16 g_wo_hi[(size_t)H_DIM * H_DIM];
__device__ __nv_bfloat16 g_wo_lo[(size_t)H_DIM * H_DIM];

// ---------------------------------------------------------------------------
// helpers
// ---------------------------------------------------------------------------
static __device__ __forceinline__ uint32_t smem_u32(const void* p) {
    uint32_t a;
    asm("{ .reg .u64 t; cvta.to.shared.u64 t, %1; cvt.u32.u64 %0, t; }"
        : "=r"(a) : "l"(p));
    return a;
}

static __device__ __forceinline__ void ldsm_x4(uint32_t* r, uint32_t addr) {
    asm volatile("ldmatrix.sync.aligned.m8n8.x4.shared.b16 {%0,%1,%2,%3}, [%4];"
                 : "=r"(r[0]), "=r"(r[1]), "=r"(r[2]), "=r"(r[3]) : "r"(addr));
}

static __device__ __forceinline__ void mma16816(float* c, const uint32_t* a,
                                                const uint32_t* b) {
    asm volatile(
        "mma.sync.aligned.m16n8k16.row.col.f32.bf16.bf16.f32 "
        "{%0,%1,%2,%3}, {%4,%5,%6,%7}, {%8,%9}, {%0,%1,%2,%3};"
        : "+f"(c[0]), "+f"(c[1]), "+f"(c[2]), "+f"(c[3])
        : "r"(a[0]), "r"(a[1]), "r"(a[2]), "r"(a[3]), "r"(b[0]), "r"(b[1]));
}

// ---------------------------------------------------------------------------
// Split-bf16 GEMM via mma.sync: C[m,n] = sum_k A[m,k]*B[n,k] + bias[n]
//   C ~= Ahi*Bhi + Ahi*Blo + Alo*Bhi   (fp32 accumulate)
// CTA tile 128x64, K-chunks of 64, 256 threads, warps 4(M) x 2(N), warp 32x32.
// ---------------------------------------------------------------------------
__global__ __launch_bounds__(256, 2) void gemm_mma3(
    const __nv_bfloat16* __restrict__ Ahi, const __nv_bfloat16* __restrict__ Alo,
    const __nv_bfloat16* __restrict__ Bhi, const __nv_bfloat16* __restrict__ Blo,
    const float* __restrict__ bias, float* __restrict__ C, int N)
{
    extern __shared__ char smem[];
    const uint32_t sbase = smem_u32(smem);
    const int tid  = threadIdx.x;
    const int lane = tid & 31;
    const int warp = tid >> 5;
    const int wm   = warp >> 1;        // 0..3 -> M offset wm*32
    const int wn   = warp & 1;         // 0..1 -> N offset wn*32
    const int m0 = blockIdx.y * GBM;
    const int n0 = blockIdx.x * GBN;

    const uint32_t sAh = sbase;
    const uint32_t sAl = sbase + SA_BYTES;
    const uint32_t sBh = sbase + 2 * SA_BYTES;
    const uint32_t sBl = sbase + 2 * SA_BYTES + SB_BYTES;

    // ldmatrix address bases (bytes within tile), kk adds kk*32
    const uint32_t aAddr = (uint32_t)(wm * 32 + (lane & 15)) * SROWB
                         + (uint32_t)(lane >> 4) * 16;
    const uint32_t bAddr = (uint32_t)(wn * 32 + ((lane >> 4) & 1) * 8 + (lane & 7)) * SROWB
                         + (uint32_t)((lane >> 3) & 1) * 16;

    float acc[2][4][4];
    #pragma unroll
    for (int mf = 0; mf < 2; mf++)
        #pragma unroll
        for (int nf = 0; nf < 4; nf++)
            #pragma unroll
            for (int i = 0; i < 4; i++) acc[mf][nf][i] = 0.0f;

    for (int ch = 0; ch < GK / GBK; ch++) {
        const int k0 = ch * GBK;

        // -- global loads (before sync: overlap with prev chunk's tail) --
        uint4 rah[4], ral[4], rbh[2], rbl[2];
        #pragma unroll
        for (int i = 0; i < 4; i++) {
            const int lin = i * 256 + tid;
            const int row = lin >> 3, chk = lin & 7;
            const size_t go = (size_t)(m0 + row) * GK + k0 + chk * 8;
            rah[i] = *reinterpret_cast<const uint4*>(Ahi + go);
            ral[i] = *reinterpret_cast<const uint4*>(Alo + go);
        }
        #pragma unroll
        for (int i = 0; i < 2; i++) {
            const int lin = i * 256 + tid;
            const int row = lin >> 3, chk = lin & 7;
            const size_t go = (size_t)(n0 + row) * GK + k0 + chk * 8;
            rbh[i] = *reinterpret_cast<const uint4*>(Bhi + go);
            rbl[i] = *reinterpret_cast<const uint4*>(Blo + go);
        }

        __syncthreads();   // all warps done reading smem of previous chunk
        #pragma unroll
        for (int i = 0; i < 4; i++) {
            const int lin = i * 256 + tid;
            const uint32_t so = (uint32_t)(lin >> 3) * SROWB + (uint32_t)(lin & 7) * 16;
            *reinterpret_cast<uint4*>(smem + so)            = rah[i];
            *reinterpret_cast<uint4*>(smem + SA_BYTES + so) = ral[i];
        }
        #pragma unroll
        for (int i = 0; i < 2; i++) {
            const int lin = i * 256 + tid;
            const uint32_t so = (uint32_t)(lin >> 3) * SROWB + (uint32_t)(lin & 7) * 16;
            *reinterpret_cast<uint4*>(smem + 2 * SA_BYTES + so)            = rbh[i];
            *reinterpret_cast<uint4*>(smem + 2 * SA_BYTES + SB_BYTES + so) = rbl[i];
        }
        __syncthreads();

        // -- compute: 4 k16 steps --
        #pragma unroll
        for (int kk = 0; kk < 4; kk++) {
            const uint32_t kb = (uint32_t)kk * 32;
            uint32_t ah[2][4], al[2][4], bh[2][4], bl[2][4];

            #pragma unroll
            for (int mf = 0; mf < 2; mf++)
                ldsm_x4(ah[mf], sAh + aAddr + (uint32_t)mf * 16 * SROWB + kb);
            #pragma unroll
            for (int p = 0; p < 2; p++)
                ldsm_x4(bh[p], sBh + bAddr + (uint32_t)p * 16 * SROWB + kb);

            #pragma unroll
            for (int mf = 0; mf < 2; mf++)
                #pragma unroll
                for (int nf = 0; nf < 4; nf++)
                    mma16816(acc[mf][nf], ah[mf], &bh[nf >> 1][(nf & 1) * 2]);

            #pragma unroll
            for (int mf = 0; mf < 2; mf++)
                ldsm_x4(al[mf], sAl + aAddr + (uint32_t)mf * 16 * SROWB + kb);
            #pragma unroll
            for (int mf = 0; mf < 2; mf++)
                #pragma unroll
                for (int nf = 0; nf < 4; nf++)
                    mma16816(acc[mf][nf], al[mf], &bh[nf >> 1][(nf & 1) * 2]);

            #pragma unroll
            for (int p = 0; p < 2; p++)
                ldsm_x4(bl[p], sBl + bAddr + (uint32_t)p * 16 * SROWB + kb);
            #pragma unroll
            for (int mf = 0; mf < 2; mf++)
                #pragma unroll
                for (int nf = 0; nf < 4; nf++)
                    mma16816(acc[mf][nf], ah[mf], &bl[nf >> 1][(nf & 1) * 2]);
        }
    }

    // -- epilogue: direct fp32 stores + bias --
    const int tq = lane & 3, qd = lane >> 2;
    #pragma unroll
    for (int mf = 0; mf < 2; mf++) {
        #pragma unroll
        for (int nf = 0; nf < 4; nf++) {
            const int col = n0 + wn * 32 + nf * 8 + tq * 2;
            const float b0 = bias[col], b1 = bias[col + 1];
            #pragma unroll
            for (int h = 0; h < 2; h++) {
                const int row = m0 + wm * 32 + mf * 16 + qd + h * 8;
                float2 o;
                o.x = acc[mf][nf][h * 2 + 0] + b0;
                o.y = acc[mf][nf][h * 2 + 1] + b1;
                *reinterpret_cast<float2*>(C + (size_t)row * N + col) = o;
            }
        }
    }
}

// ---------------------------------------------------------------------------
// split fp32 -> (bf16 hi, bf16 lo), vectorized by float4
// ---------------------------------------------------------------------------
__global__ __launch_bounds__(256) void split_kernel(
    const float* __restrict__ in, __nv_bfloat16* __restrict__ hi,
    __nv_bfloat16* __restrict__ lo, size_t n4)
{
    size_t i = (size_t)blockIdx.x * 256 + threadIdx.x;
    if (i >= n4) return;
    float4 v = reinterpret_cast<const float4*>(in)[i];
    __nv_bfloat16 h0 = __float2bfloat16_rn(v.x);
    __nv_bfloat16 h1 = __float2bfloat16_rn(v.y);
    __nv_bfloat16 h2 = __float2bfloat16_rn(v.z);
    __nv_bfloat16 h3 = __float2bfloat16_rn(v.w);
    __nv_bfloat16 l0 = __float2bfloat16_rn(v.x - __bfloat162float(h0));
    __nv_bfloat16 l1 = __float2bfloat16_rn(v.y - __bfloat162float(h1));
    __nv_bfloat16 l2 = __float2bfloat16_rn(v.z - __bfloat162float(h2));
    __nv_bfloat16 l3 = __float2bfloat16_rn(v.w - __bfloat162float(h3));
    ushort4 ph = make_ushort4(__bfloat16_as_ushort(h0), __bfloat16_as_ushort(h1),
                              __bfloat16_as_ushort(h2), __bfloat16_as_ushort(h3));
    ushort4 pl = make_ushort4(__bfloat16_as_ushort(l0), __bfloat16_as_ushort(l1),
                              __bfloat16_as_ushort(l2), __bfloat16_as_ushort(l3));
    reinterpret_cast<ushort4*>(hi)[i] = ph;
    reinterpret_cast<ushort4*>(lo)[i] = pl;
}

// ---------------------------------------------------------------------------
// LayerNorm(1536) + affine + ReLU; reads fp32 h, writes bf16 hi/lo.
// ---------------------------------------------------------------------------
__global__ __launch_bounds__(256) void ln_relu_kernel(
    const float* __restrict__ h, const float* __restrict__ g,
    const float* __restrict__ bp, __nv_bfloat16* __restrict__ ohi,
    __nv_bfloat16* __restrict__ olo)
{
    const size_t rbase = (size_t)blockIdx.x * H3;
    const float* hr = h + rbase;
    const int tid = threadIdx.x;

    float v[6];
    float s = 0.0f, ss = 0.0f;
    #pragma unroll
    for (int i = 0; i < 6; i++) {
        float x = hr[tid + i * 256];
        v[i] = x; s += x; ss += x * x;
    }
    #pragma unroll
    for (int o = 16; o > 0; o >>= 1) {
        s  += __shfl_xor_sync(0xffffffffu, s, o);
        ss += __shfl_xor_sync(0xffffffffu, ss, o);
    }
    __shared__ float red[2][8];
    const int wid = tid >> 5, lid = tid & 31;
    if (lid == 0) { red[0][wid] = s; red[1][wid] = ss; }
    __syncthreads();
    s = 0.0f; ss = 0.0f;
    #pragma unroll
    for (int w = 0; w < 8; w++) { s += red[0][w]; ss += red[1][w]; }

    const float mean = s * (1.0f / H3);
    const float var  = ss * (1.0f / H3) - mean * mean;
    const float rstd = rsqrtf(var + LN_EPS);

    #pragma unroll
    for (int i = 0; i < 6; i++) {
        const int c = tid + i * 256;
        float y = (v[i] - mean) * rstd * g[c] + bp[c];
        y = fmaxf(y, 0.0f);
        __nv_bfloat16 hi = __float2bfloat16_rn(y);
        __nv_bfloat16 lo = __float2bfloat16_rn(y - __bfloat162float(hi));
        ohi[rbase + c] = hi;
        olo[rbase + c] = lo;
    }
}

// ---------------------------------------------------------------------------
// Attention: one warp per (batch, head); reads fp32 qkv, writes bf16 hi/lo ctx.
// ---------------------------------------------------------------------------
__global__ __launch_bounds__(256) void attn_kernel(
    const float* __restrict__ qkv, __nv_bfloat16* __restrict__ chi,
    __nv_bfloat16* __restrict__ clo)
{
    const int gw   = blockIdx.x * 8 + (threadIdx.x >> 5);
    const int lane = threadIdx.x & 31;
    const int b    = gw >> 3;
    const int head = gw & 7;
    const int d0   = lane * 2;

    const float* base = qkv + (size_t)b * 3 * H3 + head * HDIM + d0;
    float2 q[3], k[3], v[3];
    #pragma unroll
    for (int t = 0; t < 3; t++) {
        const float* r = base + (size_t)t * H3;
        q[t] = *reinterpret_cast<const float2*>(r);
        k[t] = *reinterpret_cast<const float2*>(r + H_DIM);
        v[t] = *reinterpret_cast<const float2*>(r + 2 * H_DIM);
    }

    float s[3][3];
    #pragma unroll
    for (int i = 0; i < 3; i++)
        #pragma unroll
        for (int j = 0; j < 3; j++)
            s[i][j] = q[i].x * k[j].x + q[i].y * k[j].y;
    #pragma unroll
    for (int o = 16; o > 0; o >>= 1)
        #pragma unroll
        for (int i = 0; i < 3; i++)
            #pragma unroll
            for (int j = 0; j < 3; j++)
                s[i][j] += __shfl_xor_sync(0xffffffffu, s[i][j], o);

    float p[3][3];
    #pragma unroll
    for (int i = 0; i < 3; i++) {
        float a0 = s[i][0] * 0.125f, a1 = s[i][1] * 0.125f, a2 = s[i][2] * 0.125f;
        float m = fmaxf(a0, fmaxf(a1, a2));
        float e0 = expf(a0 - m), e1 = expf(a1 - m), e2 = expf(a2 - m);
        float inv = 1.0f / (e0 + e1 + e2);
        p[i][0] = e0 * inv; p[i][1] = e1 * inv; p[i][2] = e2 * inv;
    }

    #pragma unroll
    for (int i = 0; i < 3; i++) {
        float cx = p[i][0] * v[0].x + p[i][1] * v[1].x + p[i][2] * v[2].x;
        float cy = p[i][0] * v[0].y + p[i][1] * v[1].y + p[i][2] * v[2].y;
        __nv_bfloat16 hx = __float2bfloat16_rn(cx);
        __nv_bfloat16 hy = __float2bfloat16_rn(cy);
        __nv_bfloat16 lx = __float2bfloat16_rn(cx - __bfloat162float(hx));
        __nv_bfloat16 ly = __float2bfloat16_rn(cy - __bfloat162float(hy));
        const size_t o = (size_t)(b * 3 + i) * H_DIM + head * HDIM + d0;
        *reinterpret_cast<__nv_bfloat162*>(chi + o) = __nv_bfloat162(hx, hy);
        *reinterpret_cast<__nv_bfloat162*>(clo + o) = __nv_bfloat162(lx, ly);
    }
}

// ---------------------------------------------------------------------------
// Gumbel softmax over 3 tokens -> (y0|y1|y2)
// ---------------------------------------------------------------------------
__global__ __launch_bounds__(256) void gumbel_out_kernel(
    const float* __restrict__ attn, const float* __restrict__ gum,
    float* __restrict__ out)
{
    const size_t idx = (size_t)blockIdx.x * 256 + threadIdx.x;
    const size_t b = idx >> 9;
    const int    c = (int)(idx & 511);

    const float l0 = attn[(b * 3 + 0) * H_DIM + c] + gum[b * H3 + c];
    const float l1 = attn[(b * 3 + 1) * H_DIM + c] + gum[b * H3 + 512 + c];
    const float l2 = attn[(b * 3 + 2) * H_DIM + c] + gum[b * H3 + 1024 + c];

    const float m  = fmaxf(l0, fmaxf(l1, l2));
    const float e0 = expf(l0 - m), e1 = expf(l1 - m), e2 = expf(l2 - m);
    const float r  = 1.0f / (e0 + e1 + e2);

    out[idx]                            = e0 * r;
    out[(size_t)B_SZ * H_DIM + idx]     = e1 * r;
    out[(size_t)2 * B_SZ * H_DIM + idx] = e2 * r;
}

// ---------------------------------------------------------------------------
extern "C" void kernel_launch(void* const* d_in, const int* in_sizes, int n_in,
                              void* d_out, int out_size)
{
    const float* x    = (const float*)d_in[0];
    const float* W_fc = (const float*)d_in[1];
    const float* b_fc = (const float*)d_in[2];
    const float* ln_g = (const float*)d_in[3];
    const float* ln_b = (const float*)d_in[4];
    const float* Wqkv = (const float*)d_in[5];
    const float* bqkv = (const float*)d_in[6];
    const float* Wo   = (const float*)d_in[7];
    const float* bo   = (const float*)d_in[8];
    const float* gum  = (const float*)d_in[9];
    float* out = (float*)d_out;

    float *f32buf;
    __nv_bfloat16 *xhi, *xlo, *hhi, *hlo, *chi, *clo;
    __nv_bfloat16 *wfch, *wfcl, *wqh, *wql, *woh, *wol;
    cudaGetSymbolAddress((void**)&f32buf, g_f32);
    cudaGetSymbolAddress((void**)&xhi, g_x_hi);
    cudaGetSymbolAddress((void**)&xlo, g_x_lo);
    cudaGetSymbolAddress((void**)&hhi, g_h_hi);
    cudaGetSymbolAddress((void**)&hlo, g_h_lo);
    cudaGetSymbolAddress((void**)&chi, g_c_hi);
    cudaGetSymbolAddress((void**)&clo, g_c_lo);
    cudaGetSymbolAddress((void**)&wfch, g_wfc_hi);
    cudaGetSymbolAddress((void**)&wfcl, g_wfc_lo);
    cudaGetSymbolAddress((void**)&wqh, g_wqkv_hi);
    cudaGetSymbolAddress((void**)&wql, g_wqkv_lo);
    cudaGetSymbolAddress((void**)&woh, g_wo_hi);
    cudaGetSymbolAddress((void**)&wol, g_wo_lo);

    cudaFuncSetAttribute(gemm_mma3,
                         cudaFuncAttributeMaxDynamicSharedMemorySize, GEMM_SMEM);

    dim3 blk(256);

    // 0) conversions to bf16 hi/lo
    {
        size_t n4;
        n4 = (size_t)B_SZ * IN_D / 4;
        split_kernel<<<(unsigned)((n4 + 255) / 256), blk>>>(x, xhi, xlo, n4);
        n4 = (size_t)H3 * IN_D / 4;
        split_kernel<<<(unsigned)((n4 + 255) / 256), blk>>>(W_fc, wfch, wfcl, n4);
        n4 = (size_t)H3 * H_DIM / 4;
        split_kernel<<<(unsigned)((n4 + 255) / 256), blk>>>(Wqkv, wqh, wql, n4);
        n4 = (size_t)H_DIM * H_DIM / 4;
        split_kernel<<<(unsigned)((n4 + 255) / 256), blk>>>(Wo, woh, wol, n4);
    }

    // 1) h = x @ W_fc^T + b_fc   [B,1536] fp32
    gemm_mma3<<<dim3(H3 / GBN, B_SZ / GBM), blk, GEMM_SMEM>>>(
        xhi, xlo, wfch, wfcl, b_fc, f32buf, H3);

    // 2) LayerNorm + ReLU -> bf16 hi/lo  (viewed as [3B,512])
    ln_relu_kernel<<<B_SZ, blk>>>(f32buf, ln_g, ln_b, hhi, hlo);

    // 3) qkv = h2 @ Wqkv^T + bqkv  [3B,1536] fp32
    gemm_mma3<<<dim3(H3 / GBN, (3 * B_SZ) / GBM), blk, GEMM_SMEM>>>(
        hhi, hlo, wqh, wql, bqkv, f32buf, H3);

    // 4) attention -> ctx bf16 hi/lo [3B,512]
    attn_kernel<<<B_SZ, blk>>>(f32buf, chi, clo);

    // 5) attn_out = ctx @ Wo^T + bo  [3B,512] fp32
    gemm_mma3<<<dim3(H_DIM / GBN, (3 * B_SZ) / GBM), blk, GEMM_SMEM>>>(
        chi, clo, woh, wol, bo, f32buf, H_DIM);

    // 6) gumbel softmax over tokens -> out
    gumbel_out_kernel<<<(B_SZ * H_DIM) / 256, blk>>>(f32buf, gum, out);
}

// round 7
// speedup vs baseline: 2.9798x; 1.2040x over previous
#include <cuda_runtime.h>
#include <cuda_bf16.h>
#include <cstdint>
#include <math.h>

#define B_SZ   65536
#define IN_D   512
#define H_DIM  512
#define H3     1536
#define NHEAD  8
#define HDIM   64
#define LN_EPS 1e-5f

#define GK     512
#define GBM    256
#define GBN    128
#define GBK    64
#define NCH    (GK / GBK)        // 8
// per-stage smem: Ahi 32K | Alo 32K | Bhi 16K | Blo 16K = 96KB; 2 stages
#define ST_A   32768
#define ST_B   16384
#define STAGE  (2 * ST_A + 2 * ST_B)         // 98304
#define GEMM_SMEM (2 * STAGE)                // 196608

#define SW128(o) ((o) ^ (((o) >> 3) & 0x70))

// ---------------------------------------------------------------------------
// Scratch (device globals)
// ---------------------------------------------------------------------------
__device__ float g_f32[(size_t)B_SZ * 3 * H3];                 // h -> qkv -> attn_out
__device__ __nv_bfloat16 g_x_hi[(size_t)B_SZ * IN_D];
__device__ __nv_bfloat16 g_x_lo[(size_t)B_SZ * IN_D];
__device__ __nv_bfloat16 g_h_hi[(size_t)B_SZ * H3];            // viewed as [3B,512]
__device__ __nv_bfloat16 g_h_lo[(size_t)B_SZ * H3];
__device__ __nv_bfloat16 g_c_hi[(size_t)B_SZ * 3 * H_DIM];     // ctx [3B,512]
__device__ __nv_bfloat16 g_c_lo[(size_t)B_SZ * 3 * H_DIM];
__device__ __nv_bfloat16 g_wfc_hi[(size_t)H3 * IN_D];
__device__ __nv_bfloat16 g_wfc_lo[(size_t)H3 * IN_D];
__device__ __nv_bfloat16 g_wqkv_hi[(size_t)H3 * H_DIM];
__device__ __nv_bfloat16 g_wqkv_lo[(size_t)H3 * H_DIM];
__device__ __nv_bfloat16 g_wo_hi[(size_t)H_DIM * H_DIM];
__device__ __nv_bfloat16 g_wo_lo[(size_t)H_DIM * H_DIM];

// ---------------------------------------------------------------------------
// helpers
// ---------------------------------------------------------------------------
static __device__ __forceinline__ uint32_t smem_u32(const void* p) {
    uint32_t a;
    asm("{ .reg .u64 t; cvta.to.shared.u64 t, %1; cvt.u32.u64 %0, t; }"
        : "=r"(a) : "l"(p));
    return a;
}

static __device__ __forceinline__ void cp16(uint32_t saddr, const void* g) {
    asm volatile("cp.async.cg.shared.global [%0], [%1], 16;"
                 :: "r"(saddr), "l"(g));
}
#define CP_COMMIT() asm volatile("cp.async.commit_group;" ::: "memory")
#define CP_WAIT(n)  asm volatile("cp.async.wait_group %0;" :: "n"(n) : "memory")

static __device__ __forceinline__ void ldsm_x4(uint32_t* r, uint32_t addr) {
    asm volatile("ldmatrix.sync.aligned.m8n8.x4.shared.b16 {%0,%1,%2,%3}, [%4];"
                 : "=r"(r[0]), "=r"(r[1]), "=r"(r[2]), "=r"(r[3]) : "r"(addr));
}

static __device__ __forceinline__ void mma16816(float* c, const uint32_t* a,
                                                const uint32_t* b) {
    asm volatile(
        "mma.sync.aligned.m16n8k16.row.col.f32.bf16.bf16.f32 "
        "{%0,%1,%2,%3}, {%4,%5,%6,%7}, {%8,%9}, {%0,%1,%2,%3};"
        : "+f"(c[0]), "+f"(c[1]), "+f"(c[2]), "+f"(c[3])
        : "r"(a[0]), "r"(a[1]), "r"(a[2]), "r"(a[3]), "r"(b[0]), "r"(b[1]));
}

// ---------------------------------------------------------------------------
// Split-bf16 GEMM, cp.async 2-stage pipeline.
//   C[m,n] = sum_k A[m,k]*B[n,k] + bias[n],  C ~= Ahi*Bhi + Alo*Bhi + Ahi*Blo
// CTA tile 256x128, K-chunks of 64, 512 threads, warps 8(M) x 2(N), warp 32x64.
// ---------------------------------------------------------------------------
__global__ __launch_bounds__(512, 1) void gemm_mma3(
    const __nv_bfloat16* __restrict__ Ahi, const __nv_bfloat16* __restrict__ Alo,
    const __nv_bfloat16* __restrict__ Bhi, const __nv_bfloat16* __restrict__ Blo,
    const float* __restrict__ bias, float* __restrict__ C, int N)
{
    extern __shared__ char smem[];
    const uint32_t sbase = smem_u32(smem);
    const int tid  = threadIdx.x;
    const int lane = tid & 31;
    const int warp = tid >> 5;
    const int wm   = warp >> 1;        // 0..7  -> M offset wm*32
    const int wn   = warp & 1;         // 0..1  -> N offset wn*64
    const int m0 = blockIdx.y * GBM;
    const int n0 = blockIdx.x * GBN;

    // per-thread cp.async slices
    //   A: 256 rows x 8 chunks(16B) = 2048 -> 4/thread (x2 for hi/lo)
    //   B: 128 rows x 8 chunks      = 1024 -> 2/thread (x2 for hi/lo)
    const int arow[4] = { (0 * 512 + tid) >> 3, (1 * 512 + tid) >> 3,
                          (2 * 512 + tid) >> 3, (3 * 512 + tid) >> 3 };
    const int achk = tid & 7;
    const int brow[2] = { (0 * 512 + tid) >> 3, (1 * 512 + tid) >> 3 };

    float acc[2][8][4];
    #pragma unroll
    for (int mf = 0; mf < 2; mf++)
        #pragma unroll
        for (int nf = 0; nf < 8; nf++)
            #pragma unroll
            for (int i = 0; i < 4; i++) acc[mf][nf][i] = 0.0f;

    // ldmatrix per-lane base addresses (pre-swizzle components)
    const uint32_t aRow = (uint32_t)(wm * 32 + (lane & 15));
    const uint32_t aCol = (uint32_t)(lane >> 4) * 16;
    const uint32_t bRowBase = (uint32_t)(wn * 64 + ((lane >> 4) & 1) * 8 + (lane & 7));
    const uint32_t bCol = (uint32_t)((lane >> 3) & 1) * 16;

    auto load_chunk = [&](int k0, int stg) {
        const uint32_t sb = sbase + (uint32_t)stg * STAGE;
        #pragma unroll
        for (int i = 0; i < 4; i++) {
            const uint32_t so = SW128((uint32_t)arow[i] * 128 + achk * 16);
            const size_t go = (size_t)(m0 + arow[i]) * GK + k0 + achk * 8;
            cp16(sb + so,        Ahi + go);
            cp16(sb + ST_A + so, Alo + go);
        }
        #pragma unroll
        for (int i = 0; i < 2; i++) {
            const uint32_t so = SW128((uint32_t)brow[i] * 128 + achk * 16);
            const size_t go = (size_t)(n0 + brow[i]) * GK + k0 + achk * 8;
            cp16(sb + 2 * ST_A + so,        Bhi + go);
            cp16(sb + 2 * ST_A + ST_B + so, Blo + go);
        }
    };

    // prologue
    load_chunk(0, 0);
    CP_COMMIT();

    for (int ch = 0; ch < NCH; ch++) {
        if (ch + 1 < NCH) {
            load_chunk((ch + 1) * GBK, (ch + 1) & 1);
            CP_COMMIT();
            CP_WAIT(1);
        } else {
            CP_WAIT(0);
        }
        __syncthreads();

        const uint32_t sb  = sbase + (uint32_t)(ch & 1) * STAGE;
        const uint32_t sAh = sb;
        const uint32_t sAl = sb + ST_A;
        const uint32_t sBh = sb + 2 * ST_A;
        const uint32_t sBl = sb + 2 * ST_A + ST_B;

        #pragma unroll
        for (int kk = 0; kk < 4; kk++) {
            const uint32_t kb = (uint32_t)kk * 32;
            uint32_t ah[2][4], al[2][4], bh[4][4], bl[4][4];

            #pragma unroll
            for (int mf = 0; mf < 2; mf++)
                ldsm_x4(ah[mf], sAh + SW128((aRow + mf * 16) * 128 + kb + aCol));
            #pragma unroll
            for (int p = 0; p < 4; p++)
                ldsm_x4(bh[p], sBh + SW128((bRowBase + p * 16) * 128 + kb + bCol));

            // term 1: hi*hi
            #pragma unroll
            for (int mf = 0; mf < 2; mf++)
                #pragma unroll
                for (int nf = 0; nf < 8; nf++)
                    mma16816(acc[mf][nf], ah[mf], &bh[nf >> 1][(nf & 1) * 2]);

            // term 2: lo*hi
            #pragma unroll
            for (int mf = 0; mf < 2; mf++)
                ldsm_x4(al[mf], sAl + SW128((aRow + mf * 16) * 128 + kb + aCol));
            #pragma unroll
            for (int mf = 0; mf < 2; mf++)
                #pragma unroll
                for (int nf = 0; nf < 8; nf++)
                    mma16816(acc[mf][nf], al[mf], &bh[nf >> 1][(nf & 1) * 2]);

            // term 3: hi*lo
            #pragma unroll
            for (int p = 0; p < 4; p++)
                ldsm_x4(bl[p], sBl + SW128((bRowBase + p * 16) * 128 + kb + bCol));
            #pragma unroll
            for (int mf = 0; mf < 2; mf++)
                #pragma unroll
                for (int nf = 0; nf < 8; nf++)
                    mma16816(acc[mf][nf], ah[mf], &bl[nf >> 1][(nf & 1) * 2]);
        }
        __syncthreads();
    }

    // epilogue: direct fp32 stores + bias
    const int tq = lane & 3, qd = lane >> 2;
    #pragma unroll
    for (int mf = 0; mf < 2; mf++) {
        #pragma unroll
        for (int nf = 0; nf < 8; nf++) {
            const int col = n0 + wn * 64 + nf * 8 + tq * 2;
            const float b0 = bias[col], b1 = bias[col + 1];
            #pragma unroll
            for (int h = 0; h < 2; h++) {
                const int row = m0 + wm * 32 + mf * 16 + qd + h * 8;
                float2 o;
                o.x = acc[mf][nf][h * 2 + 0] + b0;
                o.y = acc[mf][nf][h * 2 + 1] + b1;
                *reinterpret_cast<float2*>(C + (size_t)row * N + col) = o;
            }
        }
    }
}

// ---------------------------------------------------------------------------
// split fp32 -> (bf16 hi, bf16 lo), vectorized by float4
// ---------------------------------------------------------------------------
__global__ __launch_bounds__(256) void split_kernel(
    const float* __restrict__ in, __nv_bfloat16* __restrict__ hi,
    __nv_bfloat16* __restrict__ lo, size_t n4)
{
    size_t i = (size_t)blockIdx.x * 256 + threadIdx.x;
    if (i >= n4) return;
    float4 v = reinterpret_cast<const float4*>(in)[i];
    __nv_bfloat16 h0 = __float2bfloat16_rn(v.x);
    __nv_bfloat16 h1 = __float2bfloat16_rn(v.y);
    __nv_bfloat16 h2 = __float2bfloat16_rn(v.z);
    __nv_bfloat16 h3 = __float2bfloat16_rn(v.w);
    __nv_bfloat16 l0 = __float2bfloat16_rn(v.x - __bfloat162float(h0));
    __nv_bfloat16 l1 = __float2bfloat16_rn(v.y - __bfloat162float(h1));
    __nv_bfloat16 l2 = __float2bfloat16_rn(v.z - __bfloat162float(h2));
    __nv_bfloat16 l3 = __float2bfloat16_rn(v.w - __bfloat162float(h3));
    ushort4 ph = make_ushort4(__bfloat16_as_ushort(h0), __bfloat16_as_ushort(h1),
                              __bfloat16_as_ushort(h2), __bfloat16_as_ushort(h3));
    ushort4 pl = make_ushort4(__bfloat16_as_ushort(l0), __bfloat16_as_ushort(l1),
                              __bfloat16_as_ushort(l2), __bfloat16_as_ushort(l3));
    reinterpret_cast<ushort4*>(hi)[i] = ph;
    reinterpret_cast<ushort4*>(lo)[i] = pl;
}

// ---------------------------------------------------------------------------
// LayerNorm(1536) + affine + ReLU; reads fp32 h, writes bf16 hi/lo.
// ---------------------------------------------------------------------------
__global__ __launch_bounds__(256) void ln_relu_kernel(
    const float* __restrict__ h, const float* __restrict__ g,
    const float* __restrict__ bp, __nv_bfloat16* __restrict__ ohi,
    __nv_bfloat16* __restrict__ olo)
{
    const size_t rbase = (size_t)blockIdx.x * H3;
    const float* hr = h + rbase;
    const int tid = threadIdx.x;

    float v[6];
    float s = 0.0f, ss = 0.0f;
    #pragma unroll
    for (int i = 0; i < 6; i++) {
        float x = hr[tid + i * 256];
        v[i] = x; s += x; ss += x * x;
    }
    #pragma unroll
    for (int o = 16; o > 0; o >>= 1) {
        s  += __shfl_xor_sync(0xffffffffu, s, o);
        ss += __shfl_xor_sync(0xffffffffu, ss, o);
    }
    __shared__ float red[2][8];
    const int wid = tid >> 5, lid = tid & 31;
    if (lid == 0) { red[0][wid] = s; red[1][wid] = ss; }
    __syncthreads();
    s = 0.0f; ss = 0.0f;
    #pragma unroll
    for (int w = 0; w < 8; w++) { s += red[0][w]; ss += red[1][w]; }

    const float mean = s * (1.0f / H3);
    const float var  = ss * (1.0f / H3) - mean * mean;
    const float rstd = rsqrtf(var + LN_EPS);

    #pragma unroll
    for (int i = 0; i < 6; i++) {
        const int c = tid + i * 256;
        float y = (v[i] - mean) * rstd * g[c] + bp[c];
        y = fmaxf(y, 0.0f);
        __nv_bfloat16 hi = __float2bfloat16_rn(y);
        __nv_bfloat16 lo = __float2bfloat16_rn(y - __bfloat162float(hi));
        ohi[rbase + c] = hi;
        olo[rbase + c] = lo;
    }
}

// ---------------------------------------------------------------------------
// Attention: one warp per (batch, head); reads fp32 qkv, writes bf16 hi/lo ctx.
// ---------------------------------------------------------------------------
__global__ __launch_bounds__(256) void attn_kernel(
    const float* __restrict__ qkv, __nv_bfloat16* __restrict__ chi,
    __nv_bfloat16* __restrict__ clo)
{
    const int gw   = blockIdx.x * 8 + (threadIdx.x >> 5);
    const int lane = threadIdx.x & 31;
    const int b    = gw >> 3;
    const int head = gw & 7;
    const int d0   = lane * 2;

    const float* base = qkv + (size_t)b * 3 * H3 + head * HDIM + d0;
    float2 q[3], k[3], v[3];
    #pragma unroll
    for (int t = 0; t < 3; t++) {
        const float* r = base + (size_t)t * H3;
        q[t] = *reinterpret_cast<const float2*>(r);
        k[t] = *reinterpret_cast<const float2*>(r + H_DIM);
        v[t] = *reinterpret_cast<const float2*>(r + 2 * H_DIM);
    }

    float s[3][3];
    #pragma unroll
    for (int i = 0; i < 3; i++)
        #pragma unroll
        for (int j = 0; j < 3; j++)
            s[i][j] = q[i].x * k[j].x + q[i].y * k[j].y;
    #pragma unroll
    for (int o = 16; o > 0; o >>= 1)
        #pragma unroll
        for (int i = 0; i < 3; i++)
            #pragma unroll
            for (int j = 0; j < 3; j++)
                s[i][j] += __shfl_xor_sync(0xffffffffu, s[i][j], o);

    float p[3][3];
    #pragma unroll
    for (int i = 0; i < 3; i++) {
        float a0 = s[i][0] * 0.125f, a1 = s[i][1] * 0.125f, a2 = s[i][2] * 0.125f;
        float m = fmaxf(a0, fmaxf(a1, a2));
        float e0 = expf(a0 - m), e1 = expf(a1 - m), e2 = expf(a2 - m);
        float inv = 1.0f / (e0 + e1 + e2);
        p[i][0] = e0 * inv; p[i][1] = e1 * inv; p[i][2] = e2 * inv;
    }

    #pragma unroll
    for (int i = 0; i < 3; i++) {
        float cx = p[i][0] * v[0].x + p[i][1] * v[1].x + p[i][2] * v[2].x;
        float cy = p[i][0] * v[0].y + p[i][1] * v[1].y + p[i][2] * v[2].y;
        __nv_bfloat16 hx = __float2bfloat16_rn(cx);
        __nv_bfloat16 hy = __float2bfloat16_rn(cy);
        __nv_bfloat16 lx = __float2bfloat16_rn(cx - __bfloat162float(hx));
        __nv_bfloat16 ly = __float2bfloat16_rn(cy - __bfloat162float(hy));
        const size_t o = (size_t)(b * 3 + i) * H_DIM + head * HDIM + d0;
        *reinterpret_cast<__nv_bfloat162*>(chi + o) = __nv_bfloat162(hx, hy);
        *reinterpret_cast<__nv_bfloat162*>(clo + o) = __nv_bfloat162(lx, ly);
    }
}

// ---------------------------------------------------------------------------
// Gumbel softmax over 3 tokens -> (y0|y1|y2)
// ---------------------------------------------------------------------------
__global__ __launch_bounds__(256) void gumbel_out_kernel(
    const float* __restrict__ attn, const float* __restrict__ gum,
    float* __restrict__ out)
{
    const size_t idx = (size_t)blockIdx.x * 256 + threadIdx.x;
    const size_t b = idx >> 9;
    const int    c = (int)(idx & 511);

    const float l0 = attn[(b * 3 + 0) * H_DIM + c] + gum[b * H3 + c];
    const float l1 = attn[(b * 3 + 1) * H_DIM + c] + gum[b * H3 + 512 + c];
    const float l2 = attn[(b * 3 + 2) * H_DIM + c] + gum[b * H3 + 1024 + c];

    const float m  = fmaxf(l0, fmaxf(l1, l2));
    const float e0 = expf(l0 - m), e1 = expf(l1 - m), e2 = expf(l2 - m);
    const float r  = 1.0f / (e0 + e1 + e2);

    out[idx]                            = e0 * r;
    out[(size_t)B_SZ * H_DIM + idx]     = e1 * r;
    out[(size_t)2 * B_SZ * H_DIM + idx] = e2 * r;
}

// ---------------------------------------------------------------------------
extern "C" void kernel_launch(void* const* d_in, const int* in_sizes, int n_in,
                              void* d_out, int out_size)
{
    const float* x    = (const float*)d_in[0];
    const float* W_fc = (const float*)d_in[1];
    const float* b_fc = (const float*)d_in[2];
    const float* ln_g = (const float*)d_in[3];
    const float* ln_b = (const float*)d_in[4];
    const float* Wqkv = (const float*)d_in[5];
    const float* bqkv = (const float*)d_in[6];
    const float* Wo   = (const float*)d_in[7];
    const float* bo   = (const float*)d_in[8];
    const float* gum  = (const float*)d_in[9];
    float* out = (float*)d_out;

    float *f32buf;
    __nv_bfloat16 *xhi, *xlo, *hhi, *hlo, *chi, *clo;
    __nv_bfloat16 *wfch, *wfcl, *wqh, *wql, *woh, *wol;
    cudaGetSymbolAddress((void**)&f32buf, g_f32);
    cudaGetSymbolAddress((void**)&xhi, g_x_hi);
    cudaGetSymbolAddress((void**)&xlo, g_x_lo);
    cudaGetSymbolAddress((void**)&hhi, g_h_hi);
    cudaGetSymbolAddress((void**)&hlo, g_h_lo);
    cudaGetSymbolAddress((void**)&chi, g_c_hi);
    cudaGetSymbolAddress((void**)&clo, g_c_lo);
    cudaGetSymbolAddress((void**)&wfch, g_wfc_hi);
    cudaGetSymbolAddress((void**)&wfcl, g_wfc_lo);
    cudaGetSymbolAddress((void**)&wqh, g_wqkv_hi);
    cudaGetSymbolAddress((void**)&wql, g_wqkv_lo);
    cudaGetSymbolAddress((void**)&woh, g_wo_hi);
    cudaGetSymbolAddress((void**)&wol, g_wo_lo);

    cudaFuncSetAttribute(gemm_mma3,
                         cudaFuncAttributeMaxDynamicSharedMemorySize, GEMM_SMEM);

    dim3 blk(256);

    // 0) conversions to bf16 hi/lo
    {
        size_t n4;
        n4 = (size_t)B_SZ * IN_D / 4;
        split_kernel<<<(unsigned)((n4 + 255) / 256), blk>>>(x, xhi, xlo, n4);
        n4 = (size_t)H3 * IN_D / 4;
        split_kernel<<<(unsigned)((n4 + 255) / 256), blk>>>(W_fc, wfch, wfcl, n4);
        n4 = (size_t)H3 * H_DIM / 4;
        split_kernel<<<(unsigned)((n4 + 255) / 256), blk>>>(Wqkv, wqh, wql, n4);
        n4 = (size_t)H_DIM * H_DIM / 4;
        split_kernel<<<(unsigned)((n4 + 255) / 256), blk>>>(Wo, woh, wol, n4);
    }

    // 1) h = x @ W_fc^T + b_fc   [B,1536] fp32
    gemm_mma3<<<dim3(H3 / GBN, B_SZ / GBM), 512, GEMM_SMEM>>>(
        xhi, xlo, wfch, wfcl, b_fc, f32buf, H3);

    // 2) LayerNorm + ReLU -> bf16 hi/lo  (viewed as [3B,512])
    ln_relu_kernel<<<B_SZ, blk>>>(f32buf, ln_g, ln_b, hhi, hlo);

    // 3) qkv = h2 @ Wqkv^T + bqkv  [3B,1536] fp32
    gemm_mma3<<<dim3(H3 / GBN, (3 * B_SZ) / GBM), 512, GEMM_SMEM>>>(
        hhi, hlo, wqh, wql, bqkv, f32buf, H3);

    // 4) attention -> ctx bf16 hi/lo [3B,512]
    attn_kernel<<<B_SZ, blk>>>(f32buf, chi, clo);

    // 5) attn_out = ctx @ Wo^T + bo  [3B,512] fp32
    gemm_mma3<<<dim3(H_DIM / GBN, (3 * B_SZ) / GBM), 512, GEMM_SMEM>>>(
        chi, clo, woh, wol, bo, f32buf, H_DIM);

    // 6) gumbel softmax over tokens -> out
    gumbel_out_kernel<<<(B_SZ * H_DIM) / 256, blk>>>(f32buf, gum, out);
}

// round 8
// speedup vs baseline: 3.8493x; 1.2918x over previous
#include <cuda_runtime.h>
#include <cuda_bf16.h>
#include <cstdint>
#include <math.h>

#define B_SZ   65536
#define IN_D   512
#define H_DIM  512
#define H3     1536
#define NHEAD  8
#define HDIM   64
#define LN_EPS 1e-5f

#define GK     512
#define GBM    128
#define GBN    128
#define GBK    32                // K per chunk (tf32)
#define NCH    (GK / GBK)        // 16
#define NSTG   3
// per stage: A 128x32xf32 = 16KB, B 16KB
#define ST_A   16384
#define STAGE  32768
#define GEMM_SMEM (NSTG * STAGE)   // 98304

#define SW128(o) ((o) ^ (((o) >> 3) & 0x70))

// ---------------------------------------------------------------------------
// Scratch (device globals)
// ---------------------------------------------------------------------------
__device__ float g_f32[(size_t)B_SZ * 3 * H3];   // h -> qkv -> attn_out
__device__ float g_aux[(size_t)B_SZ * H3];       // h2 (rounded) -> ctx (rounded)
__device__ float g_xr [(size_t)B_SZ * IN_D];     // x rounded to tf32
__device__ float g_wfc [(size_t)H3 * IN_D];
__device__ float g_wqkv[(size_t)H3 * H_DIM];
__device__ float g_wo  [(size_t)H_DIM * H_DIM];

// ---------------------------------------------------------------------------
// helpers
// ---------------------------------------------------------------------------
static __device__ __forceinline__ uint32_t smem_u32(const void* p) {
    uint32_t a;
    asm("{ .reg .u64 t; cvta.to.shared.u64 t, %1; cvt.u32.u64 %0, t; }"
        : "=r"(a) : "l"(p));
    return a;
}

static __device__ __forceinline__ float tf32r(float x) {
    float y;
    asm("cvt.rna.tf32.f32 %0, %1;" : "=f"(y) : "f"(x));
    return y;
}

static __device__ __forceinline__ void cp16(uint32_t saddr, const void* g) {
    asm volatile("cp.async.cg.shared.global [%0], [%1], 16;"
                 :: "r"(saddr), "l"(g));
}
#define CP_COMMIT() asm volatile("cp.async.commit_group;" ::: "memory")
#define CP_WAIT(n)  asm volatile("cp.async.wait_group %0;" :: "n"(n) : "memory")

static __device__ __forceinline__ void ldsm_x4(uint32_t* r, uint32_t addr) {
    asm volatile("ldmatrix.sync.aligned.m8n8.x4.shared.b16 {%0,%1,%2,%3}, [%4];"
                 : "=r"(r[0]), "=r"(r[1]), "=r"(r[2]), "=r"(r[3]) : "r"(addr));
}

static __device__ __forceinline__ void mma1688(float* c, const uint32_t* a,
                                               const uint32_t* b) {
    asm volatile(
        "mma.sync.aligned.m16n8k8.row.col.f32.tf32.tf32.f32 "
        "{%0,%1,%2,%3}, {%4,%5,%6,%7}, {%8,%9}, {%0,%1,%2,%3};"
        : "+f"(c[0]), "+f"(c[1]), "+f"(c[2]), "+f"(c[3])
        : "r"(a[0]), "r"(a[1]), "r"(a[2]), "r"(a[3]), "r"(b[0]), "r"(b[1]));
}

// ---------------------------------------------------------------------------
// Single-pass TF32 GEMM: C[m,n] = sum_k A[m,k]*B[n,k] + bias[n]
// A,B fp32 pre-rounded to tf32. CTA 128x128, 3-stage cp.async, 256 threads,
// warps 4(M) x 2(N), warp tile 32x64 (2 mf x 8 nf of m16n8k8).
// ---------------------------------------------------------------------------
__global__ __launch_bounds__(256, 2) void gemm_tf32(
    const float* __restrict__ A, const float* __restrict__ B,
    const float* __restrict__ bias, float* __restrict__ C, int N)
{
    extern __shared__ char smem[];
    const uint32_t sbase = smem_u32(smem);
    const int tid  = threadIdx.x;
    const int lane = tid & 31;
    const int warp = tid >> 5;
    const int wm   = warp >> 1;        // 0..3 -> M offset wm*32
    const int wn   = warp & 1;         // 0..1 -> N offset wn*64
    const int m0 = blockIdx.y * GBM;
    const int n0 = blockIdx.x * GBN;

    // cp.async slices: A/B each 128 rows x 8 x 16B = 1024 slots -> 4/thread
    const int srow[4] = { (0 * 256 + tid) >> 3, (1 * 256 + tid) >> 3,
                          (2 * 256 + tid) >> 3, (3 * 256 + tid) >> 3 };
    const int sunit = tid & 7;

    float acc[2][8][4];
    #pragma unroll
    for (int mf = 0; mf < 2; mf++)
        #pragma unroll
        for (int nf = 0; nf < 8; nf++)
            #pragma unroll
            for (int i = 0; i < 4; i++) acc[mf][nf][i] = 0.0f;

    // ldmatrix lane address components (tf32 rows = 128B)
    const uint32_t aRow = (uint32_t)(wm * 32 + (lane & 15));
    const uint32_t aCol = (uint32_t)(lane >> 4) * 16;
    const uint32_t bRow = (uint32_t)(wn * 64 + ((lane >> 4) & 1) * 8 + (lane & 7));
    const uint32_t bCol = (uint32_t)((lane >> 3) & 1) * 16;

    auto load_chunk = [&](int ch, int stg) {
        const uint32_t sb = sbase + (uint32_t)stg * STAGE;
        const int kc = ch * GBK;   // tf32 col offset of chunk
        #pragma unroll
        for (int i = 0; i < 4; i++) {
            const uint32_t so = SW128((uint32_t)srow[i] * 128 + sunit * 16);
            cp16(sb + so,        A + (size_t)(m0 + srow[i]) * GK + kc + sunit * 4);
            cp16(sb + ST_A + so, B + (size_t)(n0 + srow[i]) * GK + kc + sunit * 4);
        }
    };

    load_chunk(0, 0); CP_COMMIT();
    load_chunk(1, 1); CP_COMMIT();

    for (int ch = 0; ch < NCH; ch++) {
        if (ch < NCH - 1) { CP_WAIT(1); } else { CP_WAIT(0); }
        __syncthreads();
        if (ch + 2 < NCH) { load_chunk(ch + 2, (ch + 2) % NSTG); CP_COMMIT(); }

        const uint32_t sb = sbase + (uint32_t)(ch % NSTG) * STAGE;
        const uint32_t sA = sb;
        const uint32_t sB = sb + ST_A;

        #pragma unroll
        for (int kk = 0; kk < 4; kk++) {          // 4 x k8 within chunk
            const uint32_t kb = (uint32_t)kk * 32;  // bytes
            uint32_t af[2][4], bf4[4][4];
            #pragma unroll
            for (int mf = 0; mf < 2; mf++)
                ldsm_x4(af[mf], sA + SW128((aRow + mf * 16) * 128 + kb + aCol));
            #pragma unroll
            for (int p = 0; p < 4; p++)
                ldsm_x4(bf4[p], sB + SW128((bRow + p * 16) * 128 + kb + bCol));
            #pragma unroll
            for (int mf = 0; mf < 2; mf++)
                #pragma unroll
                for (int nf = 0; nf < 8; nf++)
                    mma1688(acc[mf][nf], af[mf], &bf4[nf >> 1][(nf & 1) * 2]);
        }
    }

    // epilogue: direct fp32 stores + bias
    const int tq = lane & 3, qd = lane >> 2;
    #pragma unroll
    for (int mf = 0; mf < 2; mf++) {
        #pragma unroll
        for (int nf = 0; nf < 8; nf++) {
            const int col = n0 + wn * 64 + nf * 8 + tq * 2;
            const float b0 = bias[col], b1 = bias[col + 1];
            #pragma unroll
            for (int h = 0; h < 2; h++) {
                const int row = m0 + wm * 32 + mf * 16 + qd + h * 8;
                float2 o;
                o.x = acc[mf][nf][h * 2 + 0] + b0;
                o.y = acc[mf][nf][h * 2 + 1] + b1;
                *reinterpret_cast<float2*>(C + (size_t)row * N + col) = o;
            }
        }
    }
}

// ---------------------------------------------------------------------------
// round fp32 -> tf32-precision fp32, vectorized
// ---------------------------------------------------------------------------
__global__ __launch_bounds__(256) void round_kernel(
    const float* __restrict__ in, float* __restrict__ out, size_t n4)
{
    size_t i = (size_t)blockIdx.x * 256 + threadIdx.x;
    if (i >= n4) return;
    float4 v = reinterpret_cast<const float4*>(in)[i];
    v.x = tf32r(v.x); v.y = tf32r(v.y); v.z = tf32r(v.z); v.w = tf32r(v.w);
    reinterpret_cast<float4*>(out)[i] = v;
}

// ---------------------------------------------------------------------------
// LayerNorm(1536) + affine + ReLU; writes tf32-rounded fp32.
// ---------------------------------------------------------------------------
__global__ __launch_bounds__(256) void ln_relu_kernel(
    const float* __restrict__ h, const float* __restrict__ g,
    const float* __restrict__ bp, float* __restrict__ o)
{
    const size_t rbase = (size_t)blockIdx.x * H3;
    const float* hr = h + rbase;
    const int tid = threadIdx.x;

    float v[6];
    float s = 0.0f, ss = 0.0f;
    #pragma unroll
    for (int i = 0; i < 6; i++) {
        float x = hr[tid + i * 256];
        v[i] = x; s += x; ss += x * x;
    }
    #pragma unroll
    for (int of = 16; of > 0; of >>= 1) {
        s  += __shfl_xor_sync(0xffffffffu, s, of);
        ss += __shfl_xor_sync(0xffffffffu, ss, of);
    }
    __shared__ float red[2][8];
    const int wid = tid >> 5, lid = tid & 31;
    if (lid == 0) { red[0][wid] = s; red[1][wid] = ss; }
    __syncthreads();
    s = 0.0f; ss = 0.0f;
    #pragma unroll
    for (int w = 0; w < 8; w++) { s += red[0][w]; ss += red[1][w]; }

    const float mean = s * (1.0f / H3);
    const float var  = ss * (1.0f / H3) - mean * mean;
    const float rstd = rsqrtf(var + LN_EPS);

    #pragma unroll
    for (int i = 0; i < 6; i++) {
        const int c = tid + i * 256;
        float y = (v[i] - mean) * rstd * g[c] + bp[c];
        o[rbase + c] = tf32r(fmaxf(y, 0.0f));
    }
}

// ---------------------------------------------------------------------------
// Attention: one warp per (batch, head); reads fp32 qkv, writes rounded ctx.
// ---------------------------------------------------------------------------
__global__ __launch_bounds__(256) void attn_kernel(
    const float* __restrict__ qkv, float* __restrict__ ctx)
{
    const int gw   = blockIdx.x * 8 + (threadIdx.x >> 5);
    const int lane = threadIdx.x & 31;
    const int b    = gw >> 3;
    const int head = gw & 7;
    const int d0   = lane * 2;

    const float* base = qkv + (size_t)b * 3 * H3 + head * HDIM + d0;
    float2 q[3], k[3], v[3];
    #pragma unroll
    for (int t = 0; t < 3; t++) {
        const float* r = base + (size_t)t * H3;
        q[t] = *reinterpret_cast<const float2*>(r);
        k[t] = *reinterpret_cast<const float2*>(r + H_DIM);
        v[t] = *reinterpret_cast<const float2*>(r + 2 * H_DIM);
    }

    float s[3][3];
    #pragma unroll
    for (int i = 0; i < 3; i++)
        #pragma unroll
        for (int j = 0; j < 3; j++)
            s[i][j] = q[i].x * k[j].x + q[i].y * k[j].y;
    #pragma unroll
    for (int of = 16; of > 0; of >>= 1)
        #pragma unroll
        for (int i = 0; i < 3; i++)
            #pragma unroll
            for (int j = 0; j < 3; j++)
                s[i][j] += __shfl_xor_sync(0xffffffffu, s[i][j], of);

    float p[3][3];
    #pragma unroll
    for (int i = 0; i < 3; i++) {
        float a0 = s[i][0] * 0.125f, a1 = s[i][1] * 0.125f, a2 = s[i][2] * 0.125f;
        float m = fmaxf(a0, fmaxf(a1, a2));
        float e0 = expf(a0 - m), e1 = expf(a1 - m), e2 = expf(a2 - m);
        float inv = 1.0f / (e0 + e1 + e2);
        p[i][0] = e0 * inv; p[i][1] = e1 * inv; p[i][2] = e2 * inv;
    }

    #pragma unroll
    for (int i = 0; i < 3; i++) {
        float2 c;
        c.x = tf32r(p[i][0] * v[0].x + p[i][1] * v[1].x + p[i][2] * v[2].x);
        c.y = tf32r(p[i][0] * v[0].y + p[i][1] * v[1].y + p[i][2] * v[2].y);
        *reinterpret_cast<float2*>(
            ctx + (size_t)(b * 3 + i) * H_DIM + head * HDIM + d0) = c;
    }
}

// ---------------------------------------------------------------------------
// Gumbel softmax over 3 tokens -> (y0|y1|y2)
// ---------------------------------------------------------------------------
__global__ __launch_bounds__(256) void gumbel_out_kernel(
    const float* __restrict__ attn, const float* __restrict__ gum,
    float* __restrict__ out)
{
    const size_t idx = (size_t)blockIdx.x * 256 + threadIdx.x;
    const size_t b = idx >> 9;
    const int    c = (int)(idx & 511);

    const float l0 = attn[(b * 3 + 0) * H_DIM + c] + gum[b * H3 + c];
    const float l1 = attn[(b * 3 + 1) * H_DIM + c] + gum[b * H3 + 512 + c];
    const float l2 = attn[(b * 3 + 2) * H_DIM + c] + gum[b * H3 + 1024 + c];

    const float m  = fmaxf(l0, fmaxf(l1, l2));
    const float e0 = expf(l0 - m), e1 = expf(l1 - m), e2 = expf(l2 - m);
    const float r  = 1.0f / (e0 + e1 + e2);

    out[idx]                            = e0 * r;
    out[(size_t)B_SZ * H_DIM + idx]     = e1 * r;
    out[(size_t)2 * B_SZ * H_DIM + idx] = e2 * r;
}

// ---------------------------------------------------------------------------
extern "C" void kernel_launch(void* const* d_in, const int* in_sizes, int n_in,
                              void* d_out, int out_size)
{
    const float* x    = (const float*)d_in[0];
    const float* W_fc = (const float*)d_in[1];
    const float* b_fc = (const float*)d_in[2];
    const float* ln_g = (const float*)d_in[3];
    const float* ln_b = (const float*)d_in[4];
    const float* Wqkv = (const float*)d_in[5];
    const float* bqkv = (const float*)d_in[6];
    const float* Wo   = (const float*)d_in[7];
    const float* bo   = (const float*)d_in[8];
    const float* gum  = (const float*)d_in[9];
    float* out = (float*)d_out;

    float *f32buf, *aux, *xr, *wfc, *wqkv, *wo;
    cudaGetSymbolAddress((void**)&f32buf, g_f32);
    cudaGetSymbolAddress((void**)&aux,    g_aux);
    cudaGetSymbolAddress((void**)&xr,     g_xr);
    cudaGetSymbolAddress((void**)&wfc,    g_wfc);
    cudaGetSymbolAddress((void**)&wqkv,   g_wqkv);
    cudaGetSymbolAddress((void**)&wo,     g_wo);

    cudaFuncSetAttribute(gemm_tf32,
                         cudaFuncAttributeMaxDynamicSharedMemorySize, GEMM_SMEM);

    dim3 blk(256);

    // 0) round inputs to tf32 precision
    {
        size_t n4;
        n4 = (size_t)B_SZ * IN_D / 4;
        round_kernel<<<(unsigned)((n4 + 255) / 256), blk>>>(x, xr, n4);
        n4 = (size_t)H3 * IN_D / 4;
        round_kernel<<<(unsigned)((n4 + 255) / 256), blk>>>(W_fc, wfc, n4);
        n4 = (size_t)H3 * H_DIM / 4;
        round_kernel<<<(unsigned)((n4 + 255) / 256), blk>>>(Wqkv, wqkv, n4);
        n4 = (size_t)H_DIM * H_DIM / 4;
        round_kernel<<<(unsigned)((n4 + 255) / 256), blk>>>(Wo, wo, n4);
    }

    // 1) h = x @ W_fc^T + b_fc   [B,1536]
    gemm_tf32<<<dim3(H3 / GBN, B_SZ / GBM), blk, GEMM_SMEM>>>(
        xr, wfc, b_fc, f32buf, H3);

    // 2) LayerNorm + ReLU -> rounded h2 (viewed as [3B,512])
    ln_relu_kernel<<<B_SZ, blk>>>(f32buf, ln_g, ln_b, aux);

    // 3) qkv = h2 @ Wqkv^T + bqkv  [3B,1536]
    gemm_tf32<<<dim3(H3 / GBN, (3 * B_SZ) / GBM), blk, GEMM_SMEM>>>(
        aux, wqkv, bqkv, f32buf, H3);

    // 4) attention -> rounded ctx [3B,512]
    attn_kernel<<<B_SZ, blk>>>(f32buf, aux);

    // 5) attn_out = ctx @ Wo^T + bo  [3B,512]
    gemm_tf32<<<dim3(H_DIM / GBN, (3 * B_SZ) / GBM), blk, GEMM_SMEM>>>(
        aux, wo, bo, f32buf, H_DIM);

    // 6) gumbel softmax over tokens -> out
    gumbel_out_kernel<<<(B_SZ * H_DIM) / 256, blk>>>(f32buf, gum, out);
}

// round 11
// speedup vs baseline: 5.8889x; 1.5299x over previous
#include <cuda_runtime.h>
#include <cuda_fp16.h>
#include <cstdint>
#include <math.h>

#define B_SZ   65536
#define IN_D   512
#define H_DIM  512
#define H3     1536
#define NHEAD  8
#define HDIM   64
#define LN_EPS 1e-5f

#define GK     512
#define GBM    256
#define GBN    128
#define GBK    64                // K per chunk (fp16)
#define NCH    (GK / GBK)        // 8
#define NSTG   3
// per stage: A 256x64xf16 = 32KB, B 128x64xf16 = 16KB
#define ST_A   32768
#define STAGE  49152
#define GEMM_SMEM (NSTG * STAGE)   // 147456

#define SW128(o) ((o) ^ (((o) >> 3) & 0x70))

// ---------------------------------------------------------------------------
// Scratch (device globals)
// ---------------------------------------------------------------------------
__device__ float  g_f32[(size_t)B_SZ * 3 * H3];   // h -> qkv -> attn_out
__device__ __half g_h16[(size_t)B_SZ * H3];       // h2 (fp16) -> ctx (fp16)
__device__ __half g_x16[(size_t)B_SZ * IN_D];
__device__ __half g_wfc [(size_t)H3 * IN_D];
__device__ __half g_wqkv[(size_t)H3 * H_DIM];
__device__ __half g_wo  [(size_t)H_DIM * H_DIM];

// ---------------------------------------------------------------------------
// helpers
// ---------------------------------------------------------------------------
static __device__ __forceinline__ uint32_t smem_u32(const void* p) {
    uint32_t a;
    asm("{ .reg .u64 t; cvta.to.shared.u64 t, %1; cvt.u32.u64 %0, t; }"
        : "=r"(a) : "l"(p));
    return a;
}

static __device__ __forceinline__ void cp16(uint32_t saddr, const void* g) {
    asm volatile("cp.async.cg.shared.global [%0], [%1], 16;"
                 :: "r"(saddr), "l"(g));
}
#define CP_COMMIT() asm volatile("cp.async.commit_group;" ::: "memory")
#define CP_WAIT(n)  asm volatile("cp.async.wait_group %0;" :: "n"(n) : "memory")

static __device__ __forceinline__ void ldsm_x4(uint32_t* r, uint32_t addr) {
    asm volatile("ldmatrix.sync.aligned.m8n8.x4.shared.b16 {%0,%1,%2,%3}, [%4];"
                 : "=r"(r[0]), "=r"(r[1]), "=r"(r[2]), "=r"(r[3]) : "r"(addr));
}

static __device__ __forceinline__ void mma16816(float* c, const uint32_t* a,
                                                const uint32_t* b) {
    asm volatile(
        "mma.sync.aligned.m16n8k16.row.col.f32.f16.f16.f32 "
        "{%0,%1,%2,%3}, {%4,%5,%6,%7}, {%8,%9}, {%0,%1,%2,%3};"
        : "+f"(c[0]), "+f"(c[1]), "+f"(c[2]), "+f"(c[3])
        : "r"(a[0]), "r"(a[1]), "r"(a[2]), "r"(a[3]), "r"(b[0]), "r"(b[1]));
}

// ---------------------------------------------------------------------------
// Single-pass FP16 GEMM: C[m,n] = sum_k A[m,k]*B[n,k] + bias[n]  (fp32 acc)
// CTA tile 256x128, K-chunks of 64, 3-stage cp.async, 512 threads,
// warps 8(M) x 2(N), warp tile 32x64 (2 mf x 8 nf of m16n8k16).
// ---------------------------------------------------------------------------
__global__ __launch_bounds__(512, 1) void gemm_f16(
    const __half* __restrict__ A, const __half* __restrict__ B,
    const float* __restrict__ bias, float* __restrict__ C, int N)
{
    extern __shared__ char smem[];
    const uint32_t sbase = smem_u32(smem);
    const int tid  = threadIdx.x;
    const int lane = tid & 31;
    const int warp = tid >> 5;
    const int wm   = warp >> 1;        // 0..7 -> M offset wm*32
    const int wn   = warp & 1;         // 0..1 -> N offset wn*64
    const int m0 = blockIdx.y * GBM;
    const int n0 = blockIdx.x * GBN;

    // cp.async slices: A 256 rows x 8 x 16B = 2048 -> 4/thread; B 1024 -> 2/thread
    const int arow[4] = { (0 * 512 + tid) >> 3, (1 * 512 + tid) >> 3,
                          (2 * 512 + tid) >> 3, (3 * 512 + tid) >> 3 };
    const int brow[2] = { (0 * 512 + tid) >> 3, (1 * 512 + tid) >> 3 };
    const int unit = tid & 7;

    float acc[2][8][4];
    #pragma unroll
    for (int mf = 0; mf < 2; mf++)
        #pragma unroll
        for (int nf = 0; nf < 8; nf++)
            #pragma unroll
            for (int i = 0; i < 4; i++) acc[mf][nf][i] = 0.0f;

    // ldmatrix lane address components (rows of 64 fp16 = 128B)
    const uint32_t aRow = (uint32_t)(wm * 32 + (lane & 15));
    const uint32_t aCol = (uint32_t)(lane >> 4) * 16;
    const uint32_t bRow = (uint32_t)(wn * 64 + ((lane >> 4) & 1) * 8 + (lane & 7));
    const uint32_t bCol = (uint32_t)((lane >> 3) & 1) * 16;

    auto load_chunk = [&](int ch, int stg) {
        const uint32_t sb = sbase + (uint32_t)stg * STAGE;
        const int kc = ch * GBK;       // fp16 col offset
        #pragma unroll
        for (int i = 0; i < 4; i++) {
            const uint32_t so = SW128((uint32_t)arow[i] * 128 + unit * 16);
            cp16(sb + so, A + (size_t)(m0 + arow[i]) * GK + kc + unit * 8);
        }
        #pragma unroll
        for (int i = 0; i < 2; i++) {
            const uint32_t so = SW128((uint32_t)brow[i] * 128 + unit * 16);
            cp16(sb + ST_A + so, B + (size_t)(n0 + brow[i]) * GK + kc + unit * 8);
        }
    };

    load_chunk(0, 0); CP_COMMIT();
    load_chunk(1, 1); CP_COMMIT();

    for (int ch = 0; ch < NCH; ch++) {
        if (ch < NCH - 1) { CP_WAIT(1); } else { CP_WAIT(0); }
        __syncthreads();
        if (ch + 2 < NCH) { load_chunk(ch + 2, (ch + 2) % NSTG); CP_COMMIT(); }

        const uint32_t sb = sbase + (uint32_t)(ch % NSTG) * STAGE;
        const uint32_t sA = sb;
        const uint32_t sB = sb + ST_A;

        #pragma unroll
        for (int kk = 0; kk < 4; kk++) {            // 4 x k16 within chunk
            const uint32_t kb = (uint32_t)kk * 32;  // bytes
            uint32_t af[2][4], bf4[4][4];
            #pragma unroll
            for (int mf = 0; mf < 2; mf++)
                ldsm_x4(af[mf], sA + SW128((aRow + mf * 16) * 128 + kb + aCol));
            #pragma unroll
            for (int p = 0; p < 4; p++)
                ldsm_x4(bf4[p], sB + SW128((bRow + p * 16) * 128 + kb + bCol));
            #pragma unroll
            for (int mf = 0; mf < 2; mf++)
                #pragma unroll
                for (int nf = 0; nf < 8; nf++)
                    mma16816(acc[mf][nf], af[mf], &bf4[nf >> 1][(nf & 1) * 2]);
        }
    }

    // epilogue: direct fp32 stores + bias
    const int tq = lane & 3, qd = lane >> 2;
    #pragma unroll
    for (int mf = 0; mf < 2; mf++) {
        #pragma unroll
        for (int nf = 0; nf < 8; nf++) {
            const int col = n0 + wn * 64 + nf * 8 + tq * 2;
            const float b0 = bias[col], b1 = bias[col + 1];
            #pragma unroll
            for (int h = 0; h < 2; h++) {
                const int row = m0 + wm * 32 + mf * 16 + qd + h * 8;
                float2 o;
                o.x = acc[mf][nf][h * 2 + 0] + b0;
                o.y = acc[mf][nf][h * 2 + 1] + b1;
                *reinterpret_cast<float2*>(C + (size_t)row * N + col) = o;
            }
        }
    }
}

// ---------------------------------------------------------------------------
// convert fp32 -> fp16, vectorized
// ---------------------------------------------------------------------------
__global__ __launch_bounds__(256) void cvt16_kernel(
    const float* __restrict__ in, __half* __restrict__ out, size_t n4)
{
    size_t i = (size_t)blockIdx.x * 256 + threadIdx.x;
    if (i >= n4) return;
    float4 v = reinterpret_cast<const float4*>(in)[i];
    ushort4 p;
    p.x = __half_as_ushort(__float2half_rn(v.x));
    p.y = __half_as_ushort(__float2half_rn(v.y));
    p.z = __half_as_ushort(__float2half_rn(v.z));
    p.w = __half_as_ushort(__float2half_rn(v.w));
    reinterpret_cast<ushort4*>(out)[i] = p;
}

// ---------------------------------------------------------------------------
// LayerNorm(1536) + affine + ReLU; reads fp32 h, writes fp16.
// ---------------------------------------------------------------------------
__global__ __launch_bounds__(256) void ln_relu_kernel(
    const float* __restrict__ h, const float* __restrict__ g,
    const float* __restrict__ bp, __half* __restrict__ o)
{
    const size_t rbase = (size_t)blockIdx.x * H3;
    const float* hr = h + rbase;
    const int tid = threadIdx.x;

    float v[6];
    float s = 0.0f, ss = 0.0f;
    #pragma unroll
    for (int i = 0; i < 6; i++) {
        float x = hr[tid + i * 256];
        v[i] = x; s += x; ss += x * x;
    }
    #pragma unroll
    for (int of = 16; of > 0; of >>= 1) {
        s  += __shfl_xor_sync(0xffffffffu, s, of);
        ss += __shfl_xor_sync(0xffffffffu, ss, of);
    }
    __shared__ float red[2][8];
    const int wid = tid >> 5, lid = tid & 31;
    if (lid == 0) { red[0][wid] = s; red[1][wid] = ss; }
    __syncthreads();
    s = 0.0f; ss = 0.0f;
    #pragma unroll
    for (int w = 0; w < 8; w++) { s += red[0][w]; ss += red[1][w]; }

    const float mean = s * (1.0f / H3);
    const float var  = ss * (1.0f / H3) - mean * mean;
    const float rstd = rsqrtf(var + LN_EPS);

    #pragma unroll
    for (int i = 0; i < 6; i++) {
        const int c = tid + i * 256;
        float y = (v[i] - mean) * rstd * g[c] + bp[c];
        o[rbase + c] = __float2half_rn(fmaxf(y, 0.0f));
    }
}

// ---------------------------------------------------------------------------
// Attention: one warp per (batch, head); reads fp32 qkv, writes fp16 ctx.
// ---------------------------------------------------------------------------
__global__ __launch_bounds__(256) void attn_kernel(
    const float* __restrict__ qkv, __half* __restrict__ ctx)
{
    const int gw   = blockIdx.x * 8 + (threadIdx.x >> 5);
    const int lane = threadIdx.x & 31;
    const int b    = gw >> 3;
    const int head = gw & 7;
    const int d0   = lane * 2;

    const float* base = qkv + (size_t)b * 3 * H3 + head * HDIM + d0;
    float2 q[3], k[3], v[3];
    #pragma unroll
    for (int t = 0; t < 3; t++) {
        const float* r = base + (size_t)t * H3;
        q[t] = *reinterpret_cast<const float2*>(r);
        k[t] = *reinterpret_cast<const float2*>(r + H_DIM);
        v[t] = *reinterpret_cast<const float2*>(r + 2 * H_DIM);
    }

    float s[3][3];
    #pragma unroll
    for (int i = 0; i < 3; i++)
        #pragma unroll
        for (int j = 0; j < 3; j++)
            s[i][j] = q[i].x * k[j].x + q[i].y * k[j].y;
    #pragma unroll
    for (int of = 16; of > 0; of >>= 1)
        #pragma unroll
        for (int i = 0; i < 3; i++)
            #pragma unroll
            for (int j = 0; j < 3; j++)
                s[i][j] += __shfl_xor_sync(0xffffffffu, s[i][j], of);

    float p[3][3];
    #pragma unroll
    for (int i = 0; i < 3; i++) {
        float a0 = s[i][0] * 0.125f, a1 = s[i][1] * 0.125f, a2 = s[i][2] * 0.125f;
        float m = fmaxf(a0, fmaxf(a1, a2));
        float e0 = expf(a0 - m), e1 = expf(a1 - m), e2 = expf(a2 - m);
        float inv = 1.0f / (e0 + e1 + e2);
        p[i][0] = e0 * inv; p[i][1] = e1 * inv; p[i][2] = e2 * inv;
    }

    #pragma unroll
    for (int i = 0; i < 3; i++) {
        float cx = p[i][0] * v[0].x + p[i][1] * v[1].x + p[i][2] * v[2].x;
        float cy = p[i][0] * v[0].y + p[i][1] * v[1].y + p[i][2] * v[2].y;
        const size_t o = (size_t)(b * 3 + i) * H_DIM + head * HDIM + d0;
        *reinterpret_cast<__half2*>(ctx + o) =
            __halves2half2(__float2half_rn(cx), __float2half_rn(cy));
    }
}

// ---------------------------------------------------------------------------
// Gumbel softmax over 3 tokens -> (y0|y1|y2)
// ---------------------------------------------------------------------------
__global__ __launch_bounds__(256) void gumbel_out_kernel(
    const float* __restrict__ attn, const float* __restrict__ gum,
    float* __restrict__ out)
{
    const size_t idx = (size_t)blockIdx.x * 256 + threadIdx.x;
    const size_t b = idx >> 9;
    const int    c = (int)(idx & 511);

    const float l0 = attn[(b * 3 + 0) * H_DIM + c] + gum[b * H3 + c];
    const float l1 = attn[(b * 3 + 1) * H_DIM + c] + gum[b * H3 + 512 + c];
    const float l2 = attn[(b * 3 + 2) * H_DIM + c] + gum[b * H3 + 1024 + c];

    const float m  = fmaxf(l0, fmaxf(l1, l2));
    const float e0 = expf(l0 - m), e1 = expf(l1 - m), e2 = expf(l2 - m);
    const float r  = 1.0f / (e0 + e1 + e2);

    out[idx]                            = e0 * r;
    out[(size_t)B_SZ * H_DIM + idx]     = e1 * r;
    out[(size_t)2 * B_SZ * H_DIM + idx] = e2 * r;
}

// ---------------------------------------------------------------------------
extern "C" void kernel_launch(void* const* d_in, const int* in_sizes, int n_in,
                              void* d_out, int out_size)
{
    const float* x    = (const float*)d_in[0];
    const float* W_fc = (const float*)d_in[1];
    const float* b_fc = (const float*)d_in[2];
    const float* ln_g = (const float*)d_in[3];
    const float* ln_b = (const float*)d_in[4];
    const float* Wqkv = (const float*)d_in[5];
    const float* bqkv = (const float*)d_in[6];
    const float* Wo   = (const float*)d_in[7];
    const float* bo   = (const float*)d_in[8];
    const float* gum  = (const float*)d_in[9];
    float* out = (float*)d_out;

    float *f32buf;
    __half *h16, *x16, *wfc, *wqkv, *wo;
    cudaGetSymbolAddress((void**)&f32buf, g_f32);
    cudaGetSymbolAddress((void**)&h16,    g_h16);
    cudaGetSymbolAddress((void**)&x16,    g_x16);
    cudaGetSymbolAddress((void**)&wfc,    g_wfc);
    cudaGetSymbolAddress((void**)&wqkv,   g_wqkv);
    cudaGetSymbolAddress((void**)&wo,     g_wo);

    cudaFuncSetAttribute(gemm_f16,
                         cudaFuncAttributeMaxDynamicSharedMemorySize, GEMM_SMEM);

    dim3 blk(256);

    // 0) convert inputs to fp16
    {
        size_t n4;
        n4 = (size_t)B_SZ * IN_D / 4;
        cvt16_kernel<<<(unsigned)((n4 + 255) / 256), blk>>>(x, x16, n4);
        n4 = (size_t)H3 * IN_D / 4;
        cvt16_kernel<<<(unsigned)((n4 + 255) / 256), blk>>>(W_fc, wfc, n4);
        n4 = (size_t)H3 * H_DIM / 4;
        cvt16_kernel<<<(unsigned)((n4 + 255) / 256), blk>>>(Wqkv, wqkv, n4);
        n4 = (size_t)H_DIM * H_DIM / 4;
        cvt16_kernel<<<(unsigned)((n4 + 255) / 256), blk>>>(Wo, wo, n4);
    }

    // 1) h = x @ W_fc^T + b_fc   [B,1536]
    gemm_f16<<<dim3(H3 / GBN, B_SZ / GBM), 512, GEMM_SMEM>>>(
        x16, wfc, b_fc, f32buf, H3);

    // 2) LayerNorm + ReLU -> fp16 h2 (viewed as [3B,512])
    ln_relu_kernel<<<B_SZ, blk>>>(f32buf, ln_g, ln_b, h16);

    // 3) qkv = h2 @ Wqkv^T + bqkv  [3B,1536]
    gemm_f16<<<dim3(H3 / GBN, (3 * B_SZ) / GBM), 512, GEMM_SMEM>>>(
        h16, wqkv, bqkv, f32buf, H3);

    // 4) attention -> fp16 ctx [3B,512]  (reuses h16; h2 dead)
    attn_kernel<<<B_SZ, blk>>>(f32buf, h16);

    // 5) attn_out = ctx @ Wo^T + bo  [3B,512]  (overwrites qkv; qkv dead)
    gemm_f16<<<dim3(H_DIM / GBN, (3 * B_SZ) / GBM), 512, GEMM_SMEM>>>(
        h16, wo, bo, f32buf, H_DIM);

    // 6) gumbel softmax over tokens -> out
    gumbel_out_kernel<<<(B_SZ * H_DIM) / 256, blk>>>(f32buf, gum, out);
}

// round 12
// speedup vs baseline: 6.0226x; 1.0227x over previous
#include <cuda_runtime.h>
#include <cuda_fp16.h>
#include <cstdint>
#include <math.h>

#define B_SZ   65536
#define IN_D   512
#define H_DIM  512
#define H3     1536
#define NHEAD  8
#define HDIM   64
#define LN_EPS 1e-5f

#define GK     512
#define GBM    256
#define GBN    128
#define GBK    64                // K per chunk (fp16)
#define NCH    (GK / GBK)        // 8
#define NSTG   3
// per stage: A 256x64xf16 = 32KB, B 128x64xf16 = 16KB
#define ST_A   32768
#define STAGE  49152
#define GEMM_SMEM (NSTG * STAGE)   // 147456

#define SW128(o) ((o) ^ (((o) >> 3) & 0x70))

// ---------------------------------------------------------------------------
// Scratch (device globals) — all-fp16 intermediates
//   g_a:   h [B,1536] -> h2 (in-place LN) -> ctx [3B,512] (same bytes)
//   g_qkv: qkv [3B,1536] -> attn_out [3B,512] (first third)
// ---------------------------------------------------------------------------
__device__ __half g_a  [(size_t)B_SZ * H3];
__device__ __half g_qkv[(size_t)B_SZ * 3 * H3];
__device__ __half g_x16[(size_t)B_SZ * IN_D];
__device__ __half g_wfc [(size_t)H3 * IN_D];
__device__ __half g_wqkv[(size_t)H3 * H_DIM];
__device__ __half g_wo  [(size_t)H_DIM * H_DIM];

// ---------------------------------------------------------------------------
// helpers
// ---------------------------------------------------------------------------
static __device__ __forceinline__ uint32_t smem_u32(const void* p) {
    uint32_t a;
    asm("{ .reg .u64 t; cvta.to.shared.u64 t, %1; cvt.u32.u64 %0, t; }"
        : "=r"(a) : "l"(p));
    return a;
}

static __device__ __forceinline__ void cp16(uint32_t saddr, const void* g) {
    asm volatile("cp.async.cg.shared.global [%0], [%1], 16;"
                 :: "r"(saddr), "l"(g));
}
#define CP_COMMIT() asm volatile("cp.async.commit_group;" ::: "memory")
#define CP_WAIT(n)  asm volatile("cp.async.wait_group %0;" :: "n"(n) : "memory")

static __device__ __forceinline__ void ldsm_x4(uint32_t* r, uint32_t addr) {
    asm volatile("ldmatrix.sync.aligned.m8n8.x4.shared.b16 {%0,%1,%2,%3}, [%4];"
                 : "=r"(r[0]), "=r"(r[1]), "=r"(r[2]), "=r"(r[3]) : "r"(addr));
}

static __device__ __forceinline__ void mma16816(float* c, const uint32_t* a,
                                                const uint32_t* b) {
    asm volatile(
        "mma.sync.aligned.m16n8k16.row.col.f32.f16.f16.f32 "
        "{%0,%1,%2,%3}, {%4,%5,%6,%7}, {%8,%9}, {%0,%1,%2,%3};"
        : "+f"(c[0]), "+f"(c[1]), "+f"(c[2]), "+f"(c[3])
        : "r"(a[0]), "r"(a[1]), "r"(a[2]), "r"(a[3]), "r"(b[0]), "r"(b[1]));
}

// ---------------------------------------------------------------------------
// Single-pass FP16 GEMM: C[m,n] = (half) (sum_k A[m,k]*B[n,k] + bias[n])
// fp32 accumulate; fp16 output. CTA tile 256x128, K-chunks of 64, 3-stage
// cp.async, 512 threads, warps 8(M) x 2(N), warp tile 32x64.
// ---------------------------------------------------------------------------
__global__ __launch_bounds__(512, 1) void gemm_f16(
    const __half* __restrict__ A, const __half* __restrict__ B,
    const float* __restrict__ bias, __half* __restrict__ C, int N)
{
    extern __shared__ char smem[];
    const uint32_t sbase = smem_u32(smem);
    const int tid  = threadIdx.x;
    const int lane = tid & 31;
    const int warp = tid >> 5;
    const int wm   = warp >> 1;        // 0..7 -> M offset wm*32
    const int wn   = warp & 1;         // 0..1 -> N offset wn*64
    const int m0 = blockIdx.y * GBM;
    const int n0 = blockIdx.x * GBN;

    // cp.async slices: A 256 rows x 8 x 16B = 2048 -> 4/thread; B 1024 -> 2/thread
    const int arow[4] = { (0 * 512 + tid) >> 3, (1 * 512 + tid) >> 3,
                          (2 * 512 + tid) >> 3, (3 * 512 + tid) >> 3 };
    const int brow[2] = { (0 * 512 + tid) >> 3, (1 * 512 + tid) >> 3 };
    const int unit = tid & 7;

    float acc[2][8][4];
    #pragma unroll
    for (int mf = 0; mf < 2; mf++)
        #pragma unroll
        for (int nf = 0; nf < 8; nf++)
            #pragma unroll
            for (int i = 0; i < 4; i++) acc[mf][nf][i] = 0.0f;

    // ldmatrix lane address components (rows of 64 fp16 = 128B)
    const uint32_t aRow = (uint32_t)(wm * 32 + (lane & 15));
    const uint32_t aCol = (uint32_t)(lane >> 4) * 16;
    const uint32_t bRow = (uint32_t)(wn * 64 + ((lane >> 4) & 1) * 8 + (lane & 7));
    const uint32_t bCol = (uint32_t)((lane >> 3) & 1) * 16;

    auto load_chunk = [&](int ch, int stg) {
        const uint32_t sb = sbase + (uint32_t)stg * STAGE;
        const int kc = ch * GBK;       // fp16 col offset
        #pragma unroll
        for (int i = 0; i < 4; i++) {
            const uint32_t so = SW128((uint32_t)arow[i] * 128 + unit * 16);
            cp16(sb + so, A + (size_t)(m0 + arow[i]) * GK + kc + unit * 8);
        }
        #pragma unroll
        for (int i = 0; i < 2; i++) {
            const uint32_t so = SW128((uint32_t)brow[i] * 128 + unit * 16);
            cp16(sb + ST_A + so, B + (size_t)(n0 + brow[i]) * GK + kc + unit * 8);
        }
    };

    load_chunk(0, 0); CP_COMMIT();
    load_chunk(1, 1); CP_COMMIT();

    for (int ch = 0; ch < NCH; ch++) {
        if (ch < NCH - 1) { CP_WAIT(1); } else { CP_WAIT(0); }
        __syncthreads();
        if (ch + 2 < NCH) { load_chunk(ch + 2, (ch + 2) % NSTG); CP_COMMIT(); }

        const uint32_t sb = sbase + (uint32_t)(ch % NSTG) * STAGE;
        const uint32_t sA = sb;
        const uint32_t sB = sb + ST_A;

        #pragma unroll
        for (int kk = 0; kk < 4; kk++) {            // 4 x k16 within chunk
            const uint32_t kb = (uint32_t)kk * 32;  // bytes
            uint32_t af[2][4], bf4[4][4];
            #pragma unroll
            for (int mf = 0; mf < 2; mf++)
                ldsm_x4(af[mf], sA + SW128((aRow + mf * 16) * 128 + kb + aCol));
            #pragma unroll
            for (int p = 0; p < 4; p++)
                ldsm_x4(bf4[p], sB + SW128((bRow + p * 16) * 128 + kb + bCol));
            #pragma unroll
            for (int mf = 0; mf < 2; mf++)
                #pragma unroll
                for (int nf = 0; nf < 8; nf++)
                    mma16816(acc[mf][nf], af[mf], &bf4[nf >> 1][(nf & 1) * 2]);
        }
    }

    // epilogue: bias + convert to fp16, __half2 stores
    const int tq = lane & 3, qd = lane >> 2;
    #pragma unroll
    for (int mf = 0; mf < 2; mf++) {
        #pragma unroll
        for (int nf = 0; nf < 8; nf++) {
            const int col = n0 + wn * 64 + nf * 8 + tq * 2;
            const float b0 = bias[col], b1 = bias[col + 1];
            #pragma unroll
            for (int h = 0; h < 2; h++) {
                const int row = m0 + wm * 32 + mf * 16 + qd + h * 8;
                __half2 o = __halves2half2(
                    __float2half_rn(acc[mf][nf][h * 2 + 0] + b0),
                    __float2half_rn(acc[mf][nf][h * 2 + 1] + b1));
                *reinterpret_cast<__half2*>(C + (size_t)row * N + col) = o;
            }
        }
    }
}

// ---------------------------------------------------------------------------
// convert fp32 -> fp16, vectorized
// ---------------------------------------------------------------------------
__global__ __launch_bounds__(256) void cvt16_kernel(
    const float* __restrict__ in, __half* __restrict__ out, size_t n4)
{
    size_t i = (size_t)blockIdx.x * 256 + threadIdx.x;
    if (i >= n4) return;
    float4 v = reinterpret_cast<const float4*>(in)[i];
    ushort4 p;
    p.x = __half_as_ushort(__float2half_rn(v.x));
    p.y = __half_as_ushort(__float2half_rn(v.y));
    p.z = __half_as_ushort(__float2half_rn(v.z));
    p.w = __half_as_ushort(__float2half_rn(v.w));
    reinterpret_cast<ushort4*>(out)[i] = p;
}

// ---------------------------------------------------------------------------
// LayerNorm(1536) + affine + ReLU over fp16, IN-PLACE (each thread writes
// only elements it read). One block (256 thr) per row; 3 x __half2 per thread.
// ---------------------------------------------------------------------------
__global__ __launch_bounds__(256) void ln_relu_kernel(
    __half* __restrict__ h, const float* __restrict__ g,
    const float* __restrict__ bp)
{
    const size_t rbase = (size_t)blockIdx.x * H3;
    __half2* hr2 = reinterpret_cast<__half2*>(h + rbase);   // 768 half2
    const int tid = threadIdx.x;

    float2 v[3];
    float s = 0.0f, ss = 0.0f;
    #pragma unroll
    for (int i = 0; i < 3; i++) {
        float2 f = __half22float2(hr2[tid + i * 256]);
        v[i] = f;
        s += f.x + f.y;
        ss += f.x * f.x + f.y * f.y;
    }
    #pragma unroll
    for (int of = 16; of > 0; of >>= 1) {
        s  += __shfl_xor_sync(0xffffffffu, s, of);
        ss += __shfl_xor_sync(0xffffffffu, ss, of);
    }
    __shared__ float red[2][8];
    const int wid = tid >> 5, lid = tid & 31;
    if (lid == 0) { red[0][wid] = s; red[1][wid] = ss; }
    __syncthreads();
    s = 0.0f; ss = 0.0f;
    #pragma unroll
    for (int w = 0; w < 8; w++) { s += red[0][w]; ss += red[1][w]; }

    const float mean = s * (1.0f / H3);
    const float var  = ss * (1.0f / H3) - mean * mean;
    const float rstd = rsqrtf(var + LN_EPS);

    #pragma unroll
    for (int i = 0; i < 3; i++) {
        const int c = (tid + i * 256) * 2;
        float y0 = (v[i].x - mean) * rstd * g[c]     + bp[c];
        float y1 = (v[i].y - mean) * rstd * g[c + 1] + bp[c + 1];
        hr2[tid + i * 256] = __halves2half2(
            __float2half_rn(fmaxf(y0, 0.0f)),
            __float2half_rn(fmaxf(y1, 0.0f)));
    }
}

// ---------------------------------------------------------------------------
// Attention: one warp per (batch, head); fp16 qkv -> fp16 ctx.
// ---------------------------------------------------------------------------
__global__ __launch_bounds__(256) void attn_kernel(
    const __half* __restrict__ qkv, __half* __restrict__ ctx)
{
    const int gw   = blockIdx.x * 8 + (threadIdx.x >> 5);
    const int lane = threadIdx.x & 31;
    const int b    = gw >> 3;
    const int head = gw & 7;
    const int d0   = lane * 2;

    const __half* base = qkv + (size_t)b * 3 * H3 + head * HDIM + d0;
    float2 q[3], k[3], v[3];
    #pragma unroll
    for (int t = 0; t < 3; t++) {
        const __half* r = base + (size_t)t * H3;
        q[t] = __half22float2(*reinterpret_cast<const __half2*>(r));
        k[t] = __half22float2(*reinterpret_cast<const __half2*>(r + H_DIM));
        v[t] = __half22float2(*reinterpret_cast<const __half2*>(r + 2 * H_DIM));
    }

    float s[3][3];
    #pragma unroll
    for (int i = 0; i < 3; i++)
        #pragma unroll
        for (int j = 0; j < 3; j++)
            s[i][j] = q[i].x * k[j].x + q[i].y * k[j].y;
    #pragma unroll
    for (int of = 16; of > 0; of >>= 1)
        #pragma unroll
        for (int i = 0; i < 3; i++)
            #pragma unroll
            for (int j = 0; j < 3; j++)
                s[i][j] += __shfl_xor_sync(0xffffffffu, s[i][j], of);

    float p[3][3];
    #pragma unroll
    for (int i = 0; i < 3; i++) {
        float a0 = s[i][0] * 0.125f, a1 = s[i][1] * 0.125f, a2 = s[i][2] * 0.125f;
        float m = fmaxf(a0, fmaxf(a1, a2));
        float e0 = expf(a0 - m), e1 = expf(a1 - m), e2 = expf(a2 - m);
        float inv = 1.0f / (e0 + e1 + e2);
        p[i][0] = e0 * inv; p[i][1] = e1 * inv; p[i][2] = e2 * inv;
    }

    #pragma unroll
    for (int i = 0; i < 3; i++) {
        float cx = p[i][0] * v[0].x + p[i][1] * v[1].x + p[i][2] * v[2].x;
        float cy = p[i][0] * v[0].y + p[i][1] * v[1].y + p[i][2] * v[2].y;
        const size_t o = (size_t)(b * 3 + i) * H_DIM + head * HDIM + d0;
        *reinterpret_cast<__half2*>(ctx + o) =
            __halves2half2(__float2half_rn(cx), __float2half_rn(cy));
    }
}

// ---------------------------------------------------------------------------
// Gumbel softmax over 3 tokens -> (y0|y1|y2); fp16 logits + fp32 gumbel.
// ---------------------------------------------------------------------------
__global__ __launch_bounds__(256) void gumbel_out_kernel(
    const __half* __restrict__ attn, const float* __restrict__ gum,
    float* __restrict__ out)
{
    const size_t idx = (size_t)blockIdx.x * 256 + threadIdx.x;
    const size_t b = idx >> 9;
    const int    c = (int)(idx & 511);

    const float l0 = __half2float(attn[(b * 3 + 0) * H_DIM + c]) + gum[b * H3 + c];
    const float l1 = __half2float(attn[(b * 3 + 1) * H_DIM + c]) + gum[b * H3 + 512 + c];
    const float l2 = __half2float(attn[(b * 3 + 2) * H_DIM + c]) + gum[b * H3 + 1024 + c];

    const float m  = fmaxf(l0, fmaxf(l1, l2));
    const float e0 = expf(l0 - m), e1 = expf(l1 - m), e2 = expf(l2 - m);
    const float r  = 1.0f / (e0 + e1 + e2);

    out[idx]                            = e0 * r;
    out[(size_t)B_SZ * H_DIM + idx]     = e1 * r;
    out[(size_t)2 * B_SZ * H_DIM + idx] = e2 * r;
}

// ---------------------------------------------------------------------------
extern "C" void kernel_launch(void* const* d_in, const int* in_sizes, int n_in,
                              void* d_out, int out_size)
{
    const float* x    = (const float*)d_in[0];
    const float* W_fc = (const float*)d_in[1];
    const float* b_fc = (const float*)d_in[2];
    const float* ln_g = (const float*)d_in[3];
    const float* ln_b = (const float*)d_in[4];
    const float* Wqkv = (const float*)d_in[5];
    const float* bqkv = (const float*)d_in[6];
    const float* Wo   = (const float*)d_in[7];
    const float* bo   = (const float*)d_in[8];
    const float* gum  = (const float*)d_in[9];
    float* out = (float*)d_out;

    __half *abuf, *qkvbuf, *x16, *wfc, *wqkv, *wo;
    cudaGetSymbolAddress((void**)&abuf,   g_a);
    cudaGetSymbolAddress((void**)&qkvbuf, g_qkv);
    cudaGetSymbolAddress((void**)&x16,    g_x16);
    cudaGetSymbolAddress((void**)&wfc,    g_wfc);
    cudaGetSymbolAddress((void**)&wqkv,   g_wqkv);
    cudaGetSymbolAddress((void**)&wo,     g_wo);

    cudaFuncSetAttribute(gemm_f16,
                         cudaFuncAttributeMaxDynamicSharedMemorySize, GEMM_SMEM);

    dim3 blk(256);

    // 0) convert inputs to fp16
    {
        size_t n4;
        n4 = (size_t)B_SZ * IN_D / 4;
        cvt16_kernel<<<(unsigned)((n4 + 255) / 256), blk>>>(x, x16, n4);
        n4 = (size_t)H3 * IN_D / 4;
        cvt16_kernel<<<(unsigned)((n4 + 255) / 256), blk>>>(W_fc, wfc, n4);
        n4 = (size_t)H3 * H_DIM / 4;
        cvt16_kernel<<<(unsigned)((n4 + 255) / 256), blk>>>(Wqkv, wqkv, n4);
        n4 = (size_t)H_DIM * H_DIM / 4;
        cvt16_kernel<<<(unsigned)((n4 + 255) / 256), blk>>>(Wo, wo, n4);
    }

    // 1) h = x @ W_fc^T + b_fc   [B,1536] fp16 -> abuf
    gemm_f16<<<dim3(H3 / GBN, B_SZ / GBM), 512, GEMM_SMEM>>>(
        x16, wfc, b_fc, abuf, H3);

    // 2) LayerNorm + ReLU in-place on abuf (then viewed as [3B,512])
    ln_relu_kernel<<<B_SZ, blk>>>(abuf, ln_g, ln_b);

    // 3) qkv = h2 @ Wqkv^T + bqkv  [3B,1536] fp16 -> qkvbuf
    gemm_f16<<<dim3(H3 / GBN, (3 * B_SZ) / GBM), 512, GEMM_SMEM>>>(
        abuf, wqkv, bqkv, qkvbuf, H3);

    // 4) attention -> fp16 ctx [3B,512] into abuf (h2 dead)
    attn_kernel<<<B_SZ, blk>>>(qkvbuf, abuf);

    // 5) attn_out = ctx @ Wo^T + bo  [3B,512] fp16 -> qkvbuf (qkv dead)
    gemm_f16<<<dim3(H_DIM / GBN, (3 * B_SZ) / GBM), 512, GEMM_SMEM>>>(
        abuf, wo, bo, qkvbuf, H_DIM);

    // 6) gumbel softmax over tokens -> out (fp32)
    gumbel_out_kernel<<<(B_SZ * H_DIM) / 256, blk>>>(qkvbuf, gum, out);
}

// round 16
// speedup vs baseline: 6.3116x; 1.0480x over previous
#include <cuda_runtime.h>
#include <cuda_fp16.h>
#include <cstdint>
#include <math.h>

#define B_SZ   65536
#define IN_D   512
#define H_DIM  512
#define H3     1536
#define NHEAD  8
#define HDIM   64
#define LN_EPS 1e-5f

#define GK     512
#define NCH    8                 // K chunks of 64
#define GBK    64

// GEMM1 (256x128, 512 thr) — unchanged proven shape
#define G1_BM  256
#define G1_BN  128
#define G1_STA 32768
#define G1_STAGE 49152
#define G1_SMEM (3 * G1_STAGE)     // 147456

// GEMM2+attn (96x192, 256 thr)
#define G2_BM  96
#define G2_BN  192
#define G2_STA 12288               // 96x64xf16
#define G2_STB 24576               // 192x64xf16
#define G2_STAGE (G2_STA + G2_STB) // 36864
#define G2_SMEM (3 * G2_STAGE)     // 110592

// GEMM3+gumbel (96x128, 256 thr)
#define G3_BM  96
#define G3_BN  128
#define G3_STA 12288
#define G3_STB 16384
#define G3_STAGE (G3_STA + G3_STB) // 28672
#define G3_SMEM (3 * G3_STAGE)     // 86016

#define SW128(o) ((o) ^ (((o) >> 3) & 0x70))

// ---------------------------------------------------------------------------
// Scratch
// ---------------------------------------------------------------------------
__device__ __half g_a  [(size_t)B_SZ * H3];          // h -> h2 (in-place LN)
__device__ __half g_ctx[(size_t)B_SZ * 3 * H_DIM];   // ctx [3B,512]
__device__ __half g_x16[(size_t)B_SZ * IN_D];
__device__ __half g_wfc [(size_t)H3 * IN_D];
__device__ __half g_wqkv[(size_t)H3 * H_DIM];        // PERMUTED rows
__device__ float  g_bqkv[H3];                        // permuted bias
__device__ __half g_wo  [(size_t)H_DIM * H_DIM];

// ---------------------------------------------------------------------------
// helpers
// ---------------------------------------------------------------------------
static __device__ __forceinline__ uint32_t smem_u32(const void* p) {
    uint32_t a;
    asm("{ .reg .u64 t; cvta.to.shared.u64 t, %1; cvt.u32.u64 %0, t; }"
        : "=r"(a) : "l"(p));
    return a;
}

static __device__ __forceinline__ void cp16(uint32_t saddr, const void* g) {
    asm volatile("cp.async.cg.shared.global [%0], [%1], 16;"
                 :: "r"(saddr), "l"(g));
}
#define CP_COMMIT() asm volatile("cp.async.commit_group;" ::: "memory")
#define CP_WAIT(n)  asm volatile("cp.async.wait_group %0;" :: "n"(n) : "memory")

static __device__ __forceinline__ void ldsm_x4(uint32_t* r, uint32_t addr) {
    asm volatile("ldmatrix.sync.aligned.m8n8.x4.shared.b16 {%0,%1,%2,%3}, [%4];"
                 : "=r"(r[0]), "=r"(r[1]), "=r"(r[2]), "=r"(r[3]) : "r"(addr));
}

static __device__ __forceinline__ void mma16816(float* c, const uint32_t* a,
                                                const uint32_t* b) {
    asm volatile(
        "mma.sync.aligned.m16n8k16.row.col.f32.f16.f16.f32 "
        "{%0,%1,%2,%3}, {%4,%5,%6,%7}, {%8,%9}, {%0,%1,%2,%3};"
        : "+f"(c[0]), "+f"(c[1]), "+f"(c[2]), "+f"(c[3])
        : "r"(a[0]), "r"(a[1]), "r"(a[2]), "r"(a[3]), "r"(b[0]), "r"(b[1]));
}

// ---------------------------------------------------------------------------
// GEMM1: fp16 out, 256x128, 512 threads (proven)
// ---------------------------------------------------------------------------
__global__ __launch_bounds__(512, 1) void gemm_f16(
    const __half* __restrict__ A, const __half* __restrict__ B,
    const float* __restrict__ bias, __half* __restrict__ C, int N)
{
    extern __shared__ char smem[];
    const uint32_t sbase = smem_u32(smem);
    const int tid  = threadIdx.x;
    const int lane = tid & 31;
    const int warp = tid >> 5;
    const int wm   = warp >> 1;
    const int wn   = warp & 1;
    const int m0 = blockIdx.y * G1_BM;
    const int n0 = blockIdx.x * G1_BN;

    const int arow[4] = { (0 * 512 + tid) >> 3, (1 * 512 + tid) >> 3,
                          (2 * 512 + tid) >> 3, (3 * 512 + tid) >> 3 };
    const int brow[2] = { (0 * 512 + tid) >> 3, (1 * 512 + tid) >> 3 };
    const int unit = tid & 7;

    float acc[2][8][4];
    #pragma unroll
    for (int mf = 0; mf < 2; mf++)
        #pragma unroll
        for (int nf = 0; nf < 8; nf++)
            #pragma unroll
            for (int i = 0; i < 4; i++) acc[mf][nf][i] = 0.0f;

    const uint32_t aRow = (uint32_t)(wm * 32 + (lane & 15));
    const uint32_t aCol = (uint32_t)(lane >> 4) * 16;
    const uint32_t bRow = (uint32_t)(wn * 64 + ((lane >> 4) & 1) * 8 + (lane & 7));
    const uint32_t bCol = (uint32_t)((lane >> 3) & 1) * 16;

    auto load_chunk = [&](int ch, int stg) {
        const uint32_t sb = sbase + (uint32_t)stg * G1_STAGE;
        const int kc = ch * GBK;
        #pragma unroll
        for (int i = 0; i < 4; i++) {
            const uint32_t so = SW128((uint32_t)arow[i] * 128 + unit * 16);
            cp16(sb + so, A + (size_t)(m0 + arow[i]) * GK + kc + unit * 8);
        }
        #pragma unroll
        for (int i = 0; i < 2; i++) {
            const uint32_t so = SW128((uint32_t)brow[i] * 128 + unit * 16);
            cp16(sb + G1_STA + so, B + (size_t)(n0 + brow[i]) * GK + kc + unit * 8);
        }
    };

    load_chunk(0, 0); CP_COMMIT();
    load_chunk(1, 1); CP_COMMIT();

    for (int ch = 0; ch < NCH; ch++) {
        if (ch < NCH - 1) { CP_WAIT(1); } else { CP_WAIT(0); }
        __syncthreads();
        if (ch + 2 < NCH) { load_chunk(ch + 2, (ch + 2) % 3); CP_COMMIT(); }

        const uint32_t sb = sbase + (uint32_t)(ch % 3) * G1_STAGE;
        #pragma unroll
        for (int kk = 0; kk < 4; kk++) {
            const uint32_t kb = (uint32_t)kk * 32;
            uint32_t af[2][4], bf4[4][4];
            #pragma unroll
            for (int mf = 0; mf < 2; mf++)
                ldsm_x4(af[mf], sb + SW128((aRow + mf * 16) * 128 + kb + aCol));
            #pragma unroll
            for (int p = 0; p < 4; p++)
                ldsm_x4(bf4[p], sb + G1_STA + SW128((bRow + p * 16) * 128 + kb + bCol));
            #pragma unroll
            for (int mf = 0; mf < 2; mf++)
                #pragma unroll
                for (int nf = 0; nf < 8; nf++)
                    mma16816(acc[mf][nf], af[mf], &bf4[nf >> 1][(nf & 1) * 2]);
        }
    }

    const int tq = lane & 3, qd = lane >> 2;
    #pragma unroll
    for (int mf = 0; mf < 2; mf++) {
        #pragma unroll
        for (int nf = 0; nf < 8; nf++) {
            const int col = n0 + wn * 64 + nf * 8 + tq * 2;
            const float b0 = bias[col], b1 = bias[col + 1];
            #pragma unroll
            for (int h = 0; h < 2; h++) {
                const int row = m0 + wm * 32 + mf * 16 + qd + h * 8;
                __half2 o = __halves2half2(
                    __float2half_rn(acc[mf][nf][h * 2 + 0] + b0),
                    __float2half_rn(acc[mf][nf][h * 2 + 1] + b1));
                *reinterpret_cast<__half2*>(C + (size_t)row * N + col) = o;
            }
        }
    }
}

// ---------------------------------------------------------------------------
// GEMM2 + fused attention. A = h2 [3B,512], B = Wqkv_perm [1536,512].
// N-tile 192 = one head's (q|k|v). Epilogue: stage qkv fp16 to smem,
// per-batch 3x3 attention, write ctx[3B,512] (head's 64-col slice).
// ---------------------------------------------------------------------------
__global__ __launch_bounds__(256, 2) void gemm_qkv_attn(
    const __half* __restrict__ A, const __half* __restrict__ B,
    const float* __restrict__ bias, __half* __restrict__ ctx)
{
    extern __shared__ char smem[];
    const uint32_t sbase = smem_u32(smem);
    const int tid  = threadIdx.x;
    const int lane = tid & 31;
    const int warp = tid >> 5;
    const int wm   = warp >> 2;        // 0..1 -> M offset wm*48
    const int wn   = warp & 3;         // 0..3 -> N offset wn*48
    const int m0   = blockIdx.y * G2_BM;
    const int head = blockIdx.x;
    const int n0   = head * G2_BN;

    // loaders: A 96x8=768 slots -> 3/thread; B 192x8=1536 -> 6/thread
    int arow[3], brow[6];
    #pragma unroll
    for (int i = 0; i < 3; i++) arow[i] = (i * 256 + tid) >> 3;
    #pragma unroll
    for (int i = 0; i < 6; i++) brow[i] = (i * 256 + tid) >> 3;
    const int unit = tid & 7;

    float acc[3][6][4];
    #pragma unroll
    for (int mf = 0; mf < 3; mf++)
        #pragma unroll
        for (int nf = 0; nf < 6; nf++)
            #pragma unroll
            for (int i = 0; i < 4; i++) acc[mf][nf][i] = 0.0f;

    const uint32_t aRow = (uint32_t)(wm * 48 + (lane & 15));
    const uint32_t aCol = (uint32_t)(lane >> 4) * 16;
    const uint32_t bRow = (uint32_t)(wn * 48 + ((lane >> 4) & 1) * 8 + (lane & 7));
    const uint32_t bCol = (uint32_t)((lane >> 3) & 1) * 16;

    auto load_chunk = [&](int ch, int stg) {
        const uint32_t sb = sbase + (uint32_t)stg * G2_STAGE;
        const int kc = ch * GBK;
        #pragma unroll
        for (int i = 0; i < 3; i++) {
            const uint32_t so = SW128((uint32_t)arow[i] * 128 + unit * 16);
            cp16(sb + so, A + (size_t)(m0 + arow[i]) * GK + kc + unit * 8);
        }
        #pragma unroll
        for (int i = 0; i < 6; i++) {
            const uint32_t so = SW128((uint32_t)brow[i] * 128 + unit * 16);
            cp16(sb + G2_STA + so, B + (size_t)(n0 + brow[i]) * GK + kc + unit * 8);
        }
    };

    load_chunk(0, 0); CP_COMMIT();
    load_chunk(1, 1); CP_COMMIT();

    for (int ch = 0; ch < NCH; ch++) {
        if (ch < NCH - 1) { CP_WAIT(1); } else { CP_WAIT(0); }
        __syncthreads();
        if (ch + 2 < NCH) { load_chunk(ch + 2, (ch + 2) % 3); CP_COMMIT(); }

        const uint32_t sb = sbase + (uint32_t)(ch % 3) * G2_STAGE;
        #pragma unroll
        for (int kk = 0; kk < 4; kk++) {
            const uint32_t kb = (uint32_t)kk * 32;
            uint32_t af[3][4], bf3[3][4];
            #pragma unroll
            for (int mf = 0; mf < 3; mf++)
                ldsm_x4(af[mf], sb + SW128((aRow + mf * 16) * 128 + kb + aCol));
            #pragma unroll
            for (int p = 0; p < 3; p++)
                ldsm_x4(bf3[p], sb + G2_STA + SW128((bRow + p * 16) * 128 + kb + bCol));
            #pragma unroll
            for (int mf = 0; mf < 3; mf++)
                #pragma unroll
                for (int nf = 0; nf < 6; nf++)
                    mma16816(acc[mf][nf], af[mf], &bf3[nf >> 1][(nf & 1) * 2]);
        }
    }

    // ---- epilogue: stage qkv tile (96x192 fp16) ----
    __syncthreads();                 // all warps done with stage smem
    __half* sE = reinterpret_cast<__half*>(smem);
    const int tq = lane & 3, qd = lane >> 2;
    #pragma unroll
    for (int mf = 0; mf < 3; mf++) {
        #pragma unroll
        for (int nf = 0; nf < 6; nf++) {
            const int col_l = wn * 48 + nf * 8 + tq * 2;
            const float b0 = bias[n0 + col_l], b1 = bias[n0 + col_l + 1];
            #pragma unroll
            for (int h = 0; h < 2; h++) {
                const int row_l = wm * 48 + mf * 16 + qd + h * 8;
                *reinterpret_cast<__half2*>(sE + row_l * 192 + col_l) =
                    __halves2half2(
                        __float2half_rn(acc[mf][nf][h * 2 + 0] + b0),
                        __float2half_rn(acc[mf][nf][h * 2 + 1] + b1));
            }
        }
    }
    __syncthreads();

    // ---- attention: 32 batches, 8 warps x 4 each ----
    #pragma unroll
    for (int j = 0; j < 4; j++) {
        const int bl = warp * 4 + j;                // local batch 0..31
        const size_t b = (size_t)blockIdx.y * 32 + bl;
        const __half* rb = sE + (3 * bl) * 192;

        float2 q[3], k[3], v[3];
        #pragma unroll
        for (int t = 0; t < 3; t++) {
            const __half* r = rb + t * 192;
            q[t] = __half22float2(*reinterpret_cast<const __half2*>(r + 2 * lane));
            k[t] = __half22float2(*reinterpret_cast<const __half2*>(r + 64 + 2 * lane));
            v[t] = __half22float2(*reinterpret_cast<const __half2*>(r + 128 + 2 * lane));
        }

        float s[3][3];
        #pragma unroll
        for (int i = 0; i < 3; i++)
            #pragma unroll
            for (int jj = 0; jj < 3; jj++)
                s[i][jj] = q[i].x * k[jj].x + q[i].y * k[jj].y;
        #pragma unroll
        for (int of = 16; of > 0; of >>= 1)
            #pragma unroll
            for (int i = 0; i < 3; i++)
                #pragma unroll
                for (int jj = 0; jj < 3; jj++)
                    s[i][jj] += __shfl_xor_sync(0xffffffffu, s[i][jj], of);

        float p[3][3];
        #pragma unroll
        for (int i = 0; i < 3; i++) {
            float a0 = s[i][0] * 0.125f, a1 = s[i][1] * 0.125f, a2 = s[i][2] * 0.125f;
            float m = fmaxf(a0, fmaxf(a1, a2));
            float e0 = expf(a0 - m), e1 = expf(a1 - m), e2 = expf(a2 - m);
            float inv = 1.0f / (e0 + e1 + e2);
            p[i][0] = e0 * inv; p[i][1] = e1 * inv; p[i][2] = e2 * inv;
        }

        #pragma unroll
        for (int i = 0; i < 3; i++) {
            float cx = p[i][0] * v[0].x + p[i][1] * v[1].x + p[i][2] * v[2].x;
            float cy = p[i][0] * v[0].y + p[i][1] * v[1].y + p[i][2] * v[2].y;
            *reinterpret_cast<__half2*>(
                ctx + (b * 3 + i) * H_DIM + head * HDIM + 2 * lane) =
                __halves2half2(__float2half_rn(cx), __float2half_rn(cy));
        }
    }
}

// ---------------------------------------------------------------------------
// GEMM3 + fused gumbel softmax. A = ctx [3B,512], B = Wo [512,512].
// GBM=96 (32 batches x 3 tokens). Epilogue: stage fp32 tile, softmax over
// token triples with gumbel noise, write 3 output slabs (fp32).
// ---------------------------------------------------------------------------
__global__ __launch_bounds__(256, 2) void gemm_out_gumbel(
    const __half* __restrict__ A, const __half* __restrict__ B,
    const float* __restrict__ bias, const float* __restrict__ gum,
    float* __restrict__ out)
{
    extern __shared__ char smem[];
    const uint32_t sbase = smem_u32(smem);
    const int tid  = threadIdx.x;
    const int lane = tid & 31;
    const int warp = tid >> 5;
    const int wm   = warp >> 2;        // 0..1 -> M offset wm*48
    const int wn   = warp & 3;         // 0..3 -> N offset wn*32
    const int m0 = blockIdx.y * G3_BM;
    const int n0 = blockIdx.x * G3_BN;

    int arow[3], brow[4];
    #pragma unroll
    for (int i = 0; i < 3; i++) arow[i] = (i * 256 + tid) >> 3;
    #pragma unroll
    for (int i = 0; i < 4; i++) brow[i] = (i * 256 + tid) >> 3;
    const int unit = tid & 7;

    float acc[3][4][4];
    #pragma unroll
    for (int mf = 0; mf < 3; mf++)
        #pragma unroll
        for (int nf = 0; nf < 4; nf++)
            #pragma unroll
            for (int i = 0; i < 4; i++) acc[mf][nf][i] = 0.0f;

    const uint32_t aRow = (uint32_t)(wm * 48 + (lane & 15));
    const uint32_t aCol = (uint32_t)(lane >> 4) * 16;
    const uint32_t bRow = (uint32_t)(wn * 32 + ((lane >> 4) & 1) * 8 + (lane & 7));
    const uint32_t bCol = (uint32_t)((lane >> 3) & 1) * 16;

    auto load_chunk = [&](int ch, int stg) {
        const uint32_t sb = sbase + (uint32_t)stg * G3_STAGE;
        const int kc = ch * GBK;
        #pragma unroll
        for (int i = 0; i < 3; i++) {
            const uint32_t so = SW128((uint32_t)arow[i] * 128 + unit * 16);
            cp16(sb + so, A + (size_t)(m0 + arow[i]) * GK + kc + unit * 8);
        }
        #pragma unroll
        for (int i = 0; i < 4; i++) {
            const uint32_t so = SW128((uint32_t)brow[i] * 128 + unit * 16);
            cp16(sb + G3_STA + so, B + (size_t)(n0 + brow[i]) * GK + kc + unit * 8);
        }
    };

    load_chunk(0, 0); CP_COMMIT();
    load_chunk(1, 1); CP_COMMIT();

    for (int ch = 0; ch < NCH; ch++) {
        if (ch < NCH - 1) { CP_WAIT(1); } else { CP_WAIT(0); }
        __syncthreads();
        if (ch + 2 < NCH) { load_chunk(ch + 2, (ch + 2) % 3); CP_COMMIT(); }

        const uint32_t sb = sbase + (uint32_t)(ch % 3) * G3_STAGE;
        #pragma unroll
        for (int kk = 0; kk < 4; kk++) {
            const uint32_t kb = (uint32_t)kk * 32;
            uint32_t af[3][4], bf2[2][4];
            #pragma unroll
            for (int mf = 0; mf < 3; mf++)
                ldsm_x4(af[mf], sb + SW128((aRow + mf * 16) * 128 + kb + aCol));
            #pragma unroll
            for (int p = 0; p < 2; p++)
                ldsm_x4(bf2[p], sb + G3_STA + SW128((bRow + p * 16) * 128 + kb + bCol));
            #pragma unroll
            for (int mf = 0; mf < 3; mf++)
                #pragma unroll
                for (int nf = 0; nf < 4; nf++)
                    mma16816(acc[mf][nf], af[mf], &bf2[nf >> 1][(nf & 1) * 2]);
        }
    }

    // ---- epilogue: stage logits fp32 (stride 132) ----
    __syncthreads();
    float* sF = reinterpret_cast<float*>(smem);
    const int tq = lane & 3, qd = lane >> 2;
    #pragma unroll
    for (int mf = 0; mf < 3; mf++) {
        #pragma unroll
        for (int nf = 0; nf < 4; nf++) {
            const int col_l = wn * 32 + nf * 8 + tq * 2;
            const float b0 = bias[n0 + col_l], b1 = bias[n0 + col_l + 1];
            #pragma unroll
            for (int h = 0; h < 2; h++) {
                const int row_l = wm * 48 + mf * 16 + qd + h * 8;
                float2 o;
                o.x = acc[mf][nf][h * 2 + 0] + b0;
                o.y = acc[mf][nf][h * 2 + 1] + b1;
                *reinterpret_cast<float2*>(sF + row_l * 132 + col_l) = o;
            }
        }
    }
    __syncthreads();

    // ---- gumbel softmax over token triples: 32 batches x 128 cols ----
    #pragma unroll
    for (int it = 0; it < 16; it++) {
        const int idx = it * 256 + tid;          // 0..4095
        const int bl = idx >> 7;                 // local batch
        const int c  = idx & 127;
        const size_t b = (size_t)blockIdx.y * 32 + bl;
        const int col = n0 + c;

        const float l0 = sF[(3 * bl + 0) * 132 + c] + gum[b * H3 + 0 * H_DIM * 1 + col];
        const float l1 = sF[(3 * bl + 1) * 132 + c] + gum[b * H3 + 512 + col];
        const float l2 = sF[(3 * bl + 2) * 132 + c] + gum[b * H3 + 1024 + col];

        const float m  = fmaxf(l0, fmaxf(l1, l2));
        const float e0 = expf(l0 - m), e1 = expf(l1 - m), e2 = expf(l2 - m);
        const float r  = 1.0f / (e0 + e1 + e2);

        out[b * 512 + col]                            = e0 * r;
        out[(size_t)B_SZ * 512 + b * 512 + col]       = e1 * r;
        out[(size_t)2 * B_SZ * 512 + b * 512 + col]   = e2 * r;
    }
}

// ---------------------------------------------------------------------------
// conversions
// ---------------------------------------------------------------------------
__global__ __launch_bounds__(256) void cvt16_kernel(
    const float* __restrict__ in, __half* __restrict__ out, size_t n4)
{
    size_t i = (size_t)blockIdx.x * 256 + threadIdx.x;
    if (i >= n4) return;
    float4 v = reinterpret_cast<const float4*>(in)[i];
    ushort4 p;
    p.x = __half_as_ushort(__float2half_rn(v.x));
    p.y = __half_as_ushort(__float2half_rn(v.y));
    p.z = __half_as_ushort(__float2half_rn(v.z));
    p.w = __half_as_ushort(__float2half_rn(v.w));
    reinterpret_cast<ushort4*>(out)[i] = p;
}

// Permute Wqkv rows to [head][q|k|v][64] order and convert to fp16.
__global__ __launch_bounds__(256) void cvt_wqkv_perm(
    const float* __restrict__ W, const float* __restrict__ bias,
    __half* __restrict__ Wp, float* __restrict__ biasp)
{
    const int idx = blockIdx.x * 256 + threadIdx.x;     // 1536*128
    const int rp = idx >> 7;
    const int k4 = (idx & 127) * 4;
    const int head = rp / 192, rem = rp % 192, sec = rem / 64, d = rem % 64;
    const int ro = sec * H_DIM + head * HDIM + d;       // sec*512 + head*64 + d

    float4 v = *reinterpret_cast<const float4*>(W + (size_t)ro * GK + k4);
    ushort4 p;
    p.x = __half_as_ushort(__float2half_rn(v.x));
    p.y = __half_as_ushort(__float2half_rn(v.y));
    p.z = __half_as_ushort(__float2half_rn(v.z));
    p.w = __half_as_ushort(__float2half_rn(v.w));
    *reinterpret_cast<ushort4*>(Wp + (size_t)rp * GK + k4) = p;
    if ((idx & 127) == 0) biasp[rp] = bias[ro];
}

// ---------------------------------------------------------------------------
// LayerNorm(1536) + affine + ReLU over fp16, in-place.
// ---------------------------------------------------------------------------
__global__ __launch_bounds__(256) void ln_relu_kernel(
    __half* __restrict__ h, const float* __restrict__ g,
    const float* __restrict__ bp)
{
    const size_t rbase = (size_t)blockIdx.x * H3;
    __half2* hr2 = reinterpret_cast<__half2*>(h + rbase);
    const int tid = threadIdx.x;

    float2 v[3];
    float s = 0.0f, ss = 0.0f;
    #pragma unroll
    for (int i = 0; i < 3; i++) {
        float2 f = __half22float2(hr2[tid + i * 256]);
        v[i] = f;
        s += f.x + f.y;
        ss += f.x * f.x + f.y * f.y;
    }
    #pragma unroll
    for (int of = 16; of > 0; of >>= 1) {
        s  += __shfl_xor_sync(0xffffffffu, s, of);
        ss += __shfl_xor_sync(0xffffffffu, ss, of);
    }
    __shared__ float red[2][8];
    const int wid = tid >> 5, lid = tid & 31;
    if (lid == 0) { red[0][wid] = s; red[1][wid] = ss; }
    __syncthreads();
    s = 0.0f; ss = 0.0f;
    #pragma unroll
    for (int w = 0; w < 8; w++) { s += red[0][w]; ss += red[1][w]; }

    const float mean = s * (1.0f / H3);
    const float var  = ss * (1.0f / H3) - mean * mean;
    const float rstd = rsqrtf(var + LN_EPS);

    #pragma unroll
    for (int i = 0; i < 3; i++) {
        const int c = (tid + i * 256) * 2;
        float y0 = (v[i].x - mean) * rstd * g[c]     + bp[c];
        float y1 = (v[i].y - mean) * rstd * g[c + 1] + bp[c + 1];
        hr2[tid + i * 256] = __halves2half2(
            __float2half_rn(fmaxf(y0, 0.0f)),
            __float2half_rn(fmaxf(y1, 0.0f)));
    }
}

// ---------------------------------------------------------------------------
extern "C" void kernel_launch(void* const* d_in, const int* in_sizes, int n_in,
                              void* d_out, int out_size)
{
    const float* x    = (const float*)d_in[0];
    const float* W_fc = (const float*)d_in[1];
    const float* b_fc = (const float*)d_in[2];
    const float* ln_g = (const float*)d_in[3];
    const float* ln_b = (const float*)d_in[4];
    const float* Wqkv = (const float*)d_in[5];
    const float* bqkv = (const float*)d_in[6];
    const float* Wo   = (const float*)d_in[7];
    const float* bo   = (const float*)d_in[8];
    const float* gum  = (const float*)d_in[9];
    float* out = (float*)d_out;

    __half *abuf, *ctxbuf, *x16, *wfc, *wqkv, *wo;
    float* bqkvp;
    cudaGetSymbolAddress((void**)&abuf,   g_a);
    cudaGetSymbolAddress((void**)&ctxbuf, g_ctx);
    cudaGetSymbolAddress((void**)&x16,    g_x16);
    cudaGetSymbolAddress((void**)&wfc,    g_wfc);
    cudaGetSymbolAddress((void**)&wqkv,   g_wqkv);
    cudaGetSymbolAddress((void**)&bqkvp,  g_bqkv);
    cudaGetSymbolAddress((void**)&wo,     g_wo);

    cudaFuncSetAttribute(gemm_f16,
                         cudaFuncAttributeMaxDynamicSharedMemorySize, G1_SMEM);
    cudaFuncSetAttribute(gemm_qkv_attn,
                         cudaFuncAttributeMaxDynamicSharedMemorySize, G2_SMEM);
    cudaFuncSetAttribute(gemm_out_gumbel,
                         cudaFuncAttributeMaxDynamicSharedMemorySize, G3_SMEM);

    dim3 blk(256);

    // 0) conversions
    {
        size_t n4;
        n4 = (size_t)B_SZ * IN_D / 4;
        cvt16_kernel<<<(unsigned)((n4 + 255) / 256), blk>>>(x, x16, n4);
        n4 = (size_t)H3 * IN_D / 4;
        cvt16_kernel<<<(unsigned)((n4 + 255) / 256), blk>>>(W_fc, wfc, n4);
        n4 = (size_t)H_DIM * H_DIM / 4;
        cvt16_kernel<<<(unsigned)((n4 + 255) / 256), blk>>>(Wo, wo, n4);
        cvt_wqkv_perm<<<(H3 * 128) / 256, blk>>>(Wqkv, bqkv, wqkv, bqkvp);
    }

    // 1) h = x @ W_fc^T + b_fc  [B,1536] fp16
    gemm_f16<<<dim3(H3 / G1_BN, B_SZ / G1_BM), 512, G1_SMEM>>>(
        x16, wfc, b_fc, abuf, H3);

    // 2) LayerNorm + ReLU in place (then viewed as [3B,512])
    ln_relu_kernel<<<B_SZ, blk>>>(abuf, ln_g, ln_b);

    // 3) qkv GEMM + attention fused -> ctx [3B,512]
    gemm_qkv_attn<<<dim3(NHEAD, (3 * B_SZ) / G2_BM), blk, G2_SMEM>>>(
        abuf, wqkv, bqkvp, ctxbuf);

    // 4) output GEMM + gumbel fused -> out (3 slabs fp32)
    gemm_out_gumbel<<<dim3(H_DIM / G3_BN, (3 * B_SZ) / G3_BM), blk, G3_SMEM>>>(
        ctxbuf, wo, bo, gum, out);
}